// round 1
// baseline (speedup 1.0000x reference)
#include <cuda_runtime.h>
#include <cuda_bf16.h>
#include <math.h>

#define BB 8
#define NN 10000
#define DD 16
#define EE 320000
#define EH 32
#define EOUT 30
#define NOUT 64
#define NB (NN*BB)            // 80000 (b,n) pairs
#define PE (BB*EE)            // 2,560,000 (b,e) pairs

// ---------------- device scratch (no allocations allowed) ----------------
__device__ __align__(16) float g_P[NB*32];        // x@W1[0:16], layout [n][b][32]
__device__ __align__(16) float g_Q[NB*32];        // x@W1[16:32]
__device__ float g_S[NB];                          // speed  per (n,b)
__device__ float g_Dd[NB];                         // direc  per (n,b)
__device__ __align__(16) float g_C[EE*32];         // b1 + ea_norm@W1[32:34] per edge
__device__ float g_inv3[EE];                       // 3/dist
__device__ float g_cdir[EE];                       // city_direc
__device__ __align__(16) float g_Ebuf[(size_t)PE*32]; // e outputs, [e][b][32] (30 used)
__device__ double g_part[256*4];
__device__ float g_stats[4];                       // mean0, invstd0, mean1, invstd1
__device__ int g_cnt[NN];
__device__ int g_off[NN+1];
__device__ int g_cursor[NN];
__device__ int g_list[2*EE];                       // signed CSR entries: (e<<1)|is_src

__device__ __forceinline__ float fsig(float x) {
    return __fdividef(1.0f, 1.0f + __expf(-x));
}

// ---------------- edge_attr stats: pass 1 (per-block partials, double) ----------------
__global__ void k_stats_partial(const float* __restrict__ ea) {
    __shared__ double sm[256][4];
    double a0=0, a1=0, a2=0, a3=0;
    for (int i = blockIdx.x*blockDim.x + threadIdx.x; i < EE; i += gridDim.x*blockDim.x) {
        float2 v = reinterpret_cast<const float2*>(ea)[i];
        a0 += (double)v.x; a1 += (double)v.x*(double)v.x;
        a2 += (double)v.y; a3 += (double)v.y*(double)v.y;
    }
    int tid = threadIdx.x;
    sm[tid][0]=a0; sm[tid][1]=a1; sm[tid][2]=a2; sm[tid][3]=a3;
    __syncthreads();
    for (int s = 128; s > 0; s >>= 1) {
        if (tid < s) {
            sm[tid][0]+=sm[tid+s][0]; sm[tid][1]+=sm[tid+s][1];
            sm[tid][2]+=sm[tid+s][2]; sm[tid][3]+=sm[tid+s][3];
        }
        __syncthreads();
    }
    if (tid == 0) {
        g_part[blockIdx.x*4+0]=sm[0][0]; g_part[blockIdx.x*4+1]=sm[0][1];
        g_part[blockIdx.x*4+2]=sm[0][2]; g_part[blockIdx.x*4+3]=sm[0][3];
    }
}

// ---------------- stats: pass 2 ----------------
__global__ void k_stats_final() {
    __shared__ double sm[256][4];
    int tid = threadIdx.x;
    sm[tid][0]=g_part[tid*4+0]; sm[tid][1]=g_part[tid*4+1];
    sm[tid][2]=g_part[tid*4+2]; sm[tid][3]=g_part[tid*4+3];
    __syncthreads();
    for (int s = 128; s > 0; s >>= 1) {
        if (tid < s) {
            sm[tid][0]+=sm[tid+s][0]; sm[tid][1]+=sm[tid+s][1];
            sm[tid][2]+=sm[tid+s][2]; sm[tid][3]+=sm[tid+s][3];
        }
        __syncthreads();
    }
    if (tid == 0) {
        double s0=sm[0][0], q0=sm[0][1], s1=sm[0][2], q1=sm[0][3];
        double m0 = s0/(double)EE;
        double m1 = s1/(double)EE;
        double v0 = (q0 - s0*s0/(double)EE) / (double)(EE-1);
        double v1 = (q1 - s1*s1/(double)EE) / (double)(EE-1);
        g_stats[0]=(float)m0; g_stats[1]=(float)(1.0/sqrt(v0));
        g_stats[2]=(float)m1; g_stats[3]=(float)(1.0/sqrt(v1));
    }
}

// ---------------- per-(b,n) precompute: P, Q, speed, direc ----------------
__global__ void k_node_pre(const float* __restrict__ x, const float* __restrict__ W1,
                           const float* __restrict__ wm, const float* __restrict__ ws) {
    __shared__ float W1s[32*32];  // rows 0..31 of W1 (35x32)
    for (int idx = threadIdx.x; idx < 32*32; idx += blockDim.x) W1s[idx] = W1[idx];
    __syncthreads();
    int pair = blockIdx.x*blockDim.x + threadIdx.x;
    if (pair >= NB) return;
    int n = pair >> 3, b = pair & 7;
    const float4* xr = reinterpret_cast<const float4*>(x + ((size_t)b*NN + n)*DD);
    float xv[16];
    #pragma unroll
    for (int d4 = 0; d4 < 4; d4++) {
        float4 v = xr[d4];
        xv[d4*4+0]=v.x; xv[d4*4+1]=v.y; xv[d4*4+2]=v.z; xv[d4*4+3]=v.w;
    }
    // P
    float4* Po = reinterpret_cast<float4*>(g_P + pair*32);
    #pragma unroll
    for (int j4 = 0; j4 < 8; j4++) {
        float4 a = make_float4(0.f,0.f,0.f,0.f);
        #pragma unroll
        for (int d = 0; d < 16; d++) {
            const float* w = &W1s[d*32 + j4*4];
            a.x += xv[d]*w[0]; a.y += xv[d]*w[1]; a.z += xv[d]*w[2]; a.w += xv[d]*w[3];
        }
        Po[j4] = a;
    }
    // Q
    float4* Qo = reinterpret_cast<float4*>(g_Q + pair*32);
    #pragma unroll
    for (int j4 = 0; j4 < 8; j4++) {
        float4 a = make_float4(0.f,0.f,0.f,0.f);
        #pragma unroll
        for (int d = 0; d < 16; d++) {
            const float* w = &W1s[(16+d)*32 + j4*4];
            a.x += xv[d]*w[0]; a.y += xv[d]*w[1]; a.z += xv[d]*w[2]; a.w += xv[d]*w[3];
        }
        Qo[j4] = a;
    }
    g_S[pair]  = xv[14]*ws[0] + wm[0];
    g_Dd[pair] = xv[15]*ws[1] + wm[1];
}

// ---------------- per-edge precompute: C = b1 + ea_norm@W1[32:34], inv3, cdir ----------------
__global__ void k_edge_pre(const float* __restrict__ ea, const float* __restrict__ W1,
                           const float* __restrict__ b1) {
    __shared__ float wA[32], wB[32], b1s[32], st[4];
    if (threadIdx.x < 32) {
        wA[threadIdx.x]  = W1[32*32 + threadIdx.x];
        wB[threadIdx.x]  = W1[33*32 + threadIdx.x];
        b1s[threadIdx.x] = b1[threadIdx.x];
    }
    if (threadIdx.x < 4) st[threadIdx.x] = g_stats[threadIdx.x];
    __syncthreads();
    int e = blockIdx.x*blockDim.x + threadIdx.x;
    if (e >= EE) return;
    float2 v = reinterpret_cast<const float2*>(ea)[e];
    g_inv3[e] = 3.0f / v.x;
    g_cdir[e] = v.y;
    float a0 = (v.x - st[0]) * st[1];
    float a1 = (v.y - st[2]) * st[3];
    float4* Co = reinterpret_cast<float4*>(g_C + e*32);
    #pragma unroll
    for (int j4 = 0; j4 < 8; j4++) {
        float4 o;
        o.x = b1s[j4*4+0] + a0*wA[j4*4+0] + a1*wB[j4*4+0];
        o.y = b1s[j4*4+1] + a0*wA[j4*4+1] + a1*wB[j4*4+1];
        o.z = b1s[j4*4+2] + a0*wA[j4*4+2] + a1*wB[j4*4+2];
        o.w = b1s[j4*4+3] + a0*wA[j4*4+3] + a1*wB[j4*4+3];
        Co[j4] = o;
    }
}

// ---------------- CSR build ----------------
__global__ void k_zero_cnt() {
    int i = blockIdx.x*blockDim.x + threadIdx.x;
    if (i < NN) g_cnt[i] = 0;
}
__global__ void k_hist(const int* __restrict__ ei) {
    int e = blockIdx.x*blockDim.x + threadIdx.x;
    if (e >= EE) return;
    atomicAdd(&g_cnt[ei[EE + e]], 1);  // tgt
    atomicAdd(&g_cnt[ei[e]], 1);       // src
}
__global__ void k_scan() {
    __shared__ int sdata[1024];
    int tid = threadIdx.x;
    int base = 0;
    for (int start = 0; start < NN; start += 1024) {
        int i = start + tid;
        int v = (i < NN) ? g_cnt[i] : 0;
        sdata[tid] = v;
        __syncthreads();
        for (int d = 1; d < 1024; d <<= 1) {
            int t = (tid >= d) ? sdata[tid - d] : 0;
            __syncthreads();
            sdata[tid] += t;
            __syncthreads();
        }
        int excl = sdata[tid] - v;
        if (i < NN) { g_off[i] = base + excl; g_cursor[i] = base + excl; }
        base += sdata[1023];
        __syncthreads();
    }
    if (tid == 0) g_off[NN] = base;
}
__global__ void k_scatter(const int* __restrict__ ei) {
    int e = blockIdx.x*blockDim.x + threadIdx.x;
    if (e >= EE) return;
    int p1 = atomicAdd(&g_cursor[ei[EE + e]], 1);
    g_list[p1] = (e << 1);           // tgt contribution: +e
    int p2 = atomicAdd(&g_cursor[ei[e]], 1);
    g_list[p2] = (e << 1) | 1;       // src contribution: -e
}

// ---------------- main per-(b,e) edge MLP ----------------
__global__ void __launch_bounds__(256) k_edge_main(const int* __restrict__ ei,
                                                   const float* __restrict__ W1,
                                                   const float* __restrict__ W2,
                                                   const float* __restrict__ b2) {
    __shared__ float W2s[32*32];   // [j][k], k padded to 32 (pad=0)
    __shared__ float w1ds[32];     // W1 row 34 (edge-weight weights)
    __shared__ float b2s[32];      // pad=0
    for (int idx = threadIdx.x; idx < 32*32; idx += blockDim.x) {
        int j = idx >> 5, k = idx & 31;
        W2s[idx] = (k < EOUT) ? W2[j*EOUT + k] : 0.f;
    }
    if (threadIdx.x < 32) {
        w1ds[threadIdx.x] = W1[34*32 + threadIdx.x];
        b2s[threadIdx.x] = (threadIdx.x < EOUT) ? b2[threadIdx.x] : 0.f;
    }
    __syncthreads();

    int p = blockIdx.x*blockDim.x + threadIdx.x;
    if (p >= PE) return;
    int e = p >> 3, b = p & 7;
    int s = ei[e], t = ei[EE + e];
    int sp = (s << 3) | b, tp = (t << 3) | b;

    float ew = g_inv3[e] * g_S[sp] * cosf(g_cdir[e] - g_Dd[sp]);
    ew = fmaxf(ew, 0.f);

    float acc[32];
    #pragma unroll
    for (int k = 0; k < 32; k++) acc[k] = b2s[k];

    const float4* Pr = reinterpret_cast<const float4*>(g_P + sp*32);
    const float4* Qr = reinterpret_cast<const float4*>(g_Q + tp*32);
    const float4* Cr = reinterpret_cast<const float4*>(g_C + e*32);

    #pragma unroll
    for (int j4 = 0; j4 < 8; j4++) {
        float4 pv = Pr[j4], qv = Qr[j4], cv = Cr[j4];
        float hh[4];
        hh[0] = fsig(pv.x + qv.x + cv.x + ew * w1ds[j4*4+0]);
        hh[1] = fsig(pv.y + qv.y + cv.y + ew * w1ds[j4*4+1]);
        hh[2] = fsig(pv.z + qv.z + cv.z + ew * w1ds[j4*4+2]);
        hh[3] = fsig(pv.w + qv.w + cv.w + ew * w1ds[j4*4+3]);
        #pragma unroll
        for (int jj = 0; jj < 4; jj++) {
            const float4* wrow = reinterpret_cast<const float4*>(&W2s[(j4*4+jj)*32]);
            float h = hh[jj];
            #pragma unroll
            for (int k4 = 0; k4 < 8; k4++) {
                float4 w = wrow[k4];
                acc[k4*4+0] += h*w.x;
                acc[k4*4+1] += h*w.y;
                acc[k4*4+2] += h*w.z;
                acc[k4*4+3] += h*w.w;
            }
        }
    }
    float4* Eo = reinterpret_cast<float4*>(g_Ebuf + (size_t)p*32);
    #pragma unroll
    for (int k4 = 0; k4 < 8; k4++) {
        float4 o;
        o.x = fsig(acc[k4*4+0]);
        o.y = fsig(acc[k4*4+1]);
        o.z = fsig(acc[k4*4+2]);
        o.w = fsig(acc[k4*4+3]);
        Eo[k4] = o;
    }
}

// ---------------- aggregate (gather CSR) + node MLP + sigmoid ----------------
__global__ void __launch_bounds__(256) k_agg_node(const float* __restrict__ Wn,
                                                  const float* __restrict__ bn,
                                                  float* __restrict__ out) {
    __shared__ float Wns[EOUT*NOUT];  // 30x64
    __shared__ float bns[NOUT];
    __shared__ float sA[8][33];
    for (int idx = threadIdx.x; idx < EOUT*NOUT; idx += blockDim.x) Wns[idx] = Wn[idx];
    if (threadIdx.x < NOUT) bns[threadIdx.x] = bn[threadIdx.x];
    __syncthreads();

    int warpId = threadIdx.x >> 5, lane = threadIdx.x & 31;
    int n = blockIdx.x;     // block = one node, warp = one batch (shared CSR list in L1)
    int b = warpId;
    int beg = g_off[n], end = g_off[n+1];

    float acc = 0.f;
    for (int i = beg; i < end; i++) {
        int entry = g_list[i];
        int row = ((entry >> 1) << 3) | b;
        float v = (lane < EOUT) ? g_Ebuf[(size_t)row*32 + lane] : 0.f;
        acc = (entry & 1) ? (acc - v) : (acc + v);
    }
    sA[warpId][lane] = (lane < EOUT) ? acc : 0.f;
    __syncwarp();

    float o0 = bns[lane], o1 = bns[lane + 32];
    #pragma unroll
    for (int j = 0; j < EOUT; j++) {
        float a = sA[warpId][j];
        o0 += a * Wns[j*NOUT + lane];
        o1 += a * Wns[j*NOUT + lane + 32];
    }
    int ob = ((b*NN + n) << 6) + lane;
    out[ob]      = fsig(o0);
    out[ob + 32] = fsig(o1);
}

// ---------------- launcher ----------------
extern "C" void kernel_launch(void* const* d_in, const int* in_sizes, int n_in,
                              void* d_out, int out_size) {
    const float* x  = (const float*)d_in[0];
    const int*   ei = (const int*)  d_in[1];
    const float* ea = (const float*)d_in[2];
    const float* wm = (const float*)d_in[3];
    const float* ws = (const float*)d_in[4];
    const float* W1 = (const float*)d_in[5];
    const float* b1 = (const float*)d_in[6];
    const float* W2 = (const float*)d_in[7];
    const float* b2 = (const float*)d_in[8];
    const float* Wn = (const float*)d_in[9];
    const float* bn = (const float*)d_in[10];
    float* out = (float*)d_out;

    k_stats_partial<<<256, 256>>>(ea);
    k_stats_final<<<1, 256>>>();
    k_node_pre<<<(NB + 255)/256, 256>>>(x, W1, wm, ws);
    k_edge_pre<<<(EE + 255)/256, 256>>>(ea, W1, b1);
    k_zero_cnt<<<(NN + 255)/256, 256>>>();
    k_hist<<<(EE + 255)/256, 256>>>(ei);
    k_scan<<<1, 1024>>>();
    k_scatter<<<(EE + 255)/256, 256>>>(ei);
    k_edge_main<<<PE/256, 256>>>(ei, W1, W2, b2);
    k_agg_node<<<NN, 256>>>(Wn, bn, out);
}

// round 3
// speedup vs baseline: 1.0913x; 1.0913x over previous
#include <cuda_runtime.h>
#include <cuda_fp16.h>
#include <cuda_bf16.h>
#include <math.h>

#define BB 8
#define NN 10000
#define DD 16
#define EE 320000
#define EH 32
#define EOUT 30
#define NOUT 64
#define NB (NN*BB)            // 80000 (b,n) pairs
#define PE (BB*EE)            // 2,560,000 (b,e) pairs

typedef unsigned long long ull;

// ---------------- device scratch ----------------
__device__ __align__(16) float g_P[NB*32];        // x@W1[0:16], layout [n][b][32]
__device__ __align__(16) float g_Q[NB*32];        // x@W1[16:32]
__device__ float g_S[NB];                          // speed  per (n,b)
__device__ float g_Dd[NB];                         // direc  per (n,b)
__device__ __align__(16) float g_C[EE*32];         // b1 + ea_norm@W1[32:34] per edge
__device__ float g_inv3[EE];                       // 3/dist
__device__ float g_cdir[EE];                       // city_direc
__device__ __align__(16) __half g_Eh[(size_t)PE*32]; // e outputs fp16, [e][b][32]
__device__ double g_part[256*4];
__device__ float g_stats[4];                       // mean0, invstd0, mean1, invstd1
__device__ int g_cnt[NN];
__device__ int g_off[NN+1];
__device__ int g_cursor[NN];
__device__ int g_list[2*EE];                       // signed CSR entries: (e<<1)|is_src

// accurate-ish sigmoid (ex2+rcp MUFU path, rel err ~1e-6)
__device__ __forceinline__ float fsig(float x) {
    return __fdividef(1.0f, 1.0f + __expf(-x));
}
// fast sigmoid via HW tanh (used for hidden layer only; error attenuated by W2)
__device__ __forceinline__ float fsig_fast(float x) {
    float t;
    asm("tanh.approx.f32 %0, %1;" : "=f"(t) : "f"(x * 0.5f));
    return fmaf(t, 0.5f, 0.5f);
}

#define FMA_F32X2(d, a, b, c) \
    asm("fma.rn.f32x2 %0, %1, %2, %3;" : "=l"(d) : "l"(a), "l"(b), "l"(c))

__device__ __forceinline__ ull pack2(float lo, float hi) {
    ull r; asm("mov.b64 %0, {%1, %2};" : "=l"(r) : "f"(lo), "f"(hi)); return r;
}
__device__ __forceinline__ void unpack2(float& lo, float& hi, ull v) {
    asm("mov.b64 {%0, %1}, %2;" : "=f"(lo), "=f"(hi) : "l"(v));
}

// ---------------- edge_attr stats: pass 1 ----------------
__global__ void k_stats_partial(const float* __restrict__ ea) {
    __shared__ double sm[256][4];
    double a0=0, a1=0, a2=0, a3=0;
    for (int i = blockIdx.x*blockDim.x + threadIdx.x; i < EE; i += gridDim.x*blockDim.x) {
        float2 v = reinterpret_cast<const float2*>(ea)[i];
        a0 += (double)v.x; a1 += (double)v.x*(double)v.x;
        a2 += (double)v.y; a3 += (double)v.y*(double)v.y;
    }
    int tid = threadIdx.x;
    sm[tid][0]=a0; sm[tid][1]=a1; sm[tid][2]=a2; sm[tid][3]=a3;
    __syncthreads();
    for (int s = 128; s > 0; s >>= 1) {
        if (tid < s) {
            sm[tid][0]+=sm[tid+s][0]; sm[tid][1]+=sm[tid+s][1];
            sm[tid][2]+=sm[tid+s][2]; sm[tid][3]+=sm[tid+s][3];
        }
        __syncthreads();
    }
    if (tid == 0) {
        g_part[blockIdx.x*4+0]=sm[0][0]; g_part[blockIdx.x*4+1]=sm[0][1];
        g_part[blockIdx.x*4+2]=sm[0][2]; g_part[blockIdx.x*4+3]=sm[0][3];
    }
}

// ---------------- stats: pass 2 ----------------
__global__ void k_stats_final() {
    __shared__ double sm[256][4];
    int tid = threadIdx.x;
    sm[tid][0]=g_part[tid*4+0]; sm[tid][1]=g_part[tid*4+1];
    sm[tid][2]=g_part[tid*4+2]; sm[tid][3]=g_part[tid*4+3];
    __syncthreads();
    for (int s = 128; s > 0; s >>= 1) {
        if (tid < s) {
            sm[tid][0]+=sm[tid+s][0]; sm[tid][1]+=sm[tid+s][1];
            sm[tid][2]+=sm[tid+s][2]; sm[tid][3]+=sm[tid+s][3];
        }
        __syncthreads();
    }
    if (tid == 0) {
        double s0=sm[0][0], q0=sm[0][1], s1=sm[0][2], q1=sm[0][3];
        double m0 = s0/(double)EE;
        double m1 = s1/(double)EE;
        double v0 = (q0 - s0*s0/(double)EE) / (double)(EE-1);
        double v1 = (q1 - s1*s1/(double)EE) / (double)(EE-1);
        g_stats[0]=(float)m0; g_stats[1]=(float)(1.0/sqrt(v0));
        g_stats[2]=(float)m1; g_stats[3]=(float)(1.0/sqrt(v1));
    }
}

// ---------------- per-(b,n) precompute: P, Q, speed, direc ----------------
__global__ void k_node_pre(const float* __restrict__ x, const float* __restrict__ W1,
                           const float* __restrict__ wm, const float* __restrict__ ws) {
    __shared__ float W1s[32*32];
    for (int idx = threadIdx.x; idx < 32*32; idx += blockDim.x) W1s[idx] = W1[idx];
    __syncthreads();
    int pair = blockIdx.x*blockDim.x + threadIdx.x;
    if (pair >= NB) return;
    int n = pair >> 3, b = pair & 7;
    const float4* xr = reinterpret_cast<const float4*>(x + ((size_t)b*NN + n)*DD);
    float xv[16];
    #pragma unroll
    for (int d4 = 0; d4 < 4; d4++) {
        float4 v = xr[d4];
        xv[d4*4+0]=v.x; xv[d4*4+1]=v.y; xv[d4*4+2]=v.z; xv[d4*4+3]=v.w;
    }
    float4* Po = reinterpret_cast<float4*>(g_P + pair*32);
    #pragma unroll
    for (int j4 = 0; j4 < 8; j4++) {
        float4 a = make_float4(0.f,0.f,0.f,0.f);
        #pragma unroll
        for (int d = 0; d < 16; d++) {
            const float* w = &W1s[d*32 + j4*4];
            a.x += xv[d]*w[0]; a.y += xv[d]*w[1]; a.z += xv[d]*w[2]; a.w += xv[d]*w[3];
        }
        Po[j4] = a;
    }
    float4* Qo = reinterpret_cast<float4*>(g_Q + pair*32);
    #pragma unroll
    for (int j4 = 0; j4 < 8; j4++) {
        float4 a = make_float4(0.f,0.f,0.f,0.f);
        #pragma unroll
        for (int d = 0; d < 16; d++) {
            const float* w = &W1s[(16+d)*32 + j4*4];
            a.x += xv[d]*w[0]; a.y += xv[d]*w[1]; a.z += xv[d]*w[2]; a.w += xv[d]*w[3];
        }
        Qo[j4] = a;
    }
    g_S[pair]  = xv[14]*ws[0] + wm[0];
    g_Dd[pair] = xv[15]*ws[1] + wm[1];
}

// ---------------- per-edge precompute: C = b1 + ea_norm@W1[32:34] ----------------
__global__ void k_edge_pre(const float* __restrict__ ea, const float* __restrict__ W1,
                           const float* __restrict__ b1) {
    __shared__ float wA[32], wB[32], b1s[32], st[4];
    if (threadIdx.x < 32) {
        wA[threadIdx.x]  = W1[32*32 + threadIdx.x];
        wB[threadIdx.x]  = W1[33*32 + threadIdx.x];
        b1s[threadIdx.x] = b1[threadIdx.x];
    }
    if (threadIdx.x < 4) st[threadIdx.x] = g_stats[threadIdx.x];
    __syncthreads();
    int e = blockIdx.x*blockDim.x + threadIdx.x;
    if (e >= EE) return;
    float2 v = reinterpret_cast<const float2*>(ea)[e];
    g_inv3[e] = 3.0f / v.x;
    g_cdir[e] = v.y;
    float a0 = (v.x - st[0]) * st[1];
    float a1 = (v.y - st[2]) * st[3];
    float4* Co = reinterpret_cast<float4*>(g_C + e*32);
    #pragma unroll
    for (int j4 = 0; j4 < 8; j4++) {
        float4 o;
        o.x = b1s[j4*4+0] + a0*wA[j4*4+0] + a1*wB[j4*4+0];
        o.y = b1s[j4*4+1] + a0*wA[j4*4+1] + a1*wB[j4*4+1];
        o.z = b1s[j4*4+2] + a0*wA[j4*4+2] + a1*wB[j4*4+2];
        o.w = b1s[j4*4+3] + a0*wA[j4*4+3] + a1*wB[j4*4+3];
        Co[j4] = o;
    }
}

// ---------------- CSR build ----------------
__global__ void k_zero_cnt() {
    int i = blockIdx.x*blockDim.x + threadIdx.x;
    if (i < NN) g_cnt[i] = 0;
}
__global__ void k_hist(const int* __restrict__ ei) {
    int e = blockIdx.x*blockDim.x + threadIdx.x;
    if (e >= EE) return;
    atomicAdd(&g_cnt[ei[EE + e]], 1);
    atomicAdd(&g_cnt[ei[e]], 1);
}
// warp-shuffle based scan, 1024 threads = 32 warps
__global__ void k_scan() {
    __shared__ int wsum[32];
    __shared__ int sbase_s;
    int tid = threadIdx.x, lane = tid & 31, w = tid >> 5;
    if (tid == 0) sbase_s = 0;
    __syncthreads();
    for (int start = 0; start < NN; start += 1024) {
        int i = start + tid;
        int v = (i < NN) ? g_cnt[i] : 0;
        int s = v;
        #pragma unroll
        for (int d = 1; d < 32; d <<= 1) {
            int t = __shfl_up_sync(0xFFFFFFFFu, s, d);
            if (lane >= d) s += t;
        }
        if (lane == 31) wsum[w] = s;
        __syncthreads();
        if (w == 0) {
            int ws = wsum[lane];
            #pragma unroll
            for (int d = 1; d < 32; d <<= 1) {
                int t = __shfl_up_sync(0xFFFFFFFFu, ws, d);
                if (lane >= d) ws += t;
            }
            wsum[lane] = ws;
        }
        __syncthreads();
        int base = sbase_s;
        int excl = base + s - v + (w > 0 ? wsum[w-1] : 0);
        if (i < NN) { g_off[i] = excl; g_cursor[i] = excl; }
        int total = wsum[31];
        __syncthreads();
        if (tid == 0) sbase_s = base + total;
        __syncthreads();
    }
    if (tid == 0) g_off[NN] = sbase_s;
}
__global__ void k_scatter(const int* __restrict__ ei) {
    int e = blockIdx.x*blockDim.x + threadIdx.x;
    if (e >= EE) return;
    int p1 = atomicAdd(&g_cursor[ei[EE + e]], 1);
    g_list[p1] = (e << 1);           // tgt contribution: +e
    int p2 = atomicAdd(&g_cursor[ei[e]], 1);
    g_list[p2] = (e << 1) | 1;       // src contribution: -e
}

// ---------------- main per-(b,e) edge MLP (FFMA2 + fp16 out) ----------------
__global__ void __launch_bounds__(256) k_edge_main(const int* __restrict__ ei,
                                                   const float* __restrict__ W1,
                                                   const float* __restrict__ W2,
                                                   const float* __restrict__ b2) {
    __shared__ __align__(16) float W2s[32*32];   // [j][k], k padded to 32
    __shared__ __align__(16) float b2s[32];
    __shared__ float w1ds[32];
    for (int idx = threadIdx.x; idx < 32*32; idx += blockDim.x) {
        int j = idx >> 5, k = idx & 31;
        W2s[idx] = (k < EOUT) ? W2[j*EOUT + k] : 0.f;
    }
    if (threadIdx.x < 32) {
        w1ds[threadIdx.x] = W1[34*32 + threadIdx.x];
        b2s[threadIdx.x] = (threadIdx.x < EOUT) ? b2[threadIdx.x] : 0.f;
    }
    __syncthreads();

    int p = blockIdx.x*blockDim.x + threadIdx.x;
    if (p >= PE) return;
    int e = p >> 3, b = p & 7;
    int s = ei[e], t = ei[EE + e];
    int sp = (s << 3) | b, tp = (t << 3) | b;

    float ew = g_inv3[e] * g_S[sp] * cosf(g_cdir[e] - g_Dd[sp]);
    ew = fmaxf(ew, 0.f);

    ull acc2[16];
    const ull* b2p = reinterpret_cast<const ull*>(b2s);
    #pragma unroll
    for (int k2 = 0; k2 < 16; k2++) acc2[k2] = b2p[k2];

    const float4* Pr = reinterpret_cast<const float4*>(g_P + sp*32);
    const float4* Qr = reinterpret_cast<const float4*>(g_Q + tp*32);
    const float4* Cr = reinterpret_cast<const float4*>(g_C + e*32);

    #pragma unroll
    for (int j4 = 0; j4 < 8; j4++) {
        float4 pv = Pr[j4], qv = Qr[j4], cv = Cr[j4];
        float hh[4];
        hh[0] = fsig_fast(pv.x + qv.x + cv.x + ew * w1ds[j4*4+0]);
        hh[1] = fsig_fast(pv.y + qv.y + cv.y + ew * w1ds[j4*4+1]);
        hh[2] = fsig_fast(pv.z + qv.z + cv.z + ew * w1ds[j4*4+2]);
        hh[3] = fsig_fast(pv.w + qv.w + cv.w + ew * w1ds[j4*4+3]);
        #pragma unroll
        for (int jj = 0; jj < 4; jj++) {
            ull hd = pack2(hh[jj], hh[jj]);
            const ulonglong2* wrow = reinterpret_cast<const ulonglong2*>(&W2s[(j4*4+jj)*32]);
            #pragma unroll
            for (int k4 = 0; k4 < 8; k4++) {
                ulonglong2 wv = wrow[k4];
                FMA_F32X2(acc2[k4*2+0], hd, wv.x, acc2[k4*2+0]);
                FMA_F32X2(acc2[k4*2+1], hd, wv.y, acc2[k4*2+1]);
            }
        }
    }
    // sigmoid (accurate) + fp16 pack + 64B store
    __align__(16) __half2 o[16];
    #pragma unroll
    for (int k2 = 0; k2 < 16; k2++) {
        float lo, hi; unpack2(lo, hi, acc2[k2]);
        o[k2] = __floats2half2_rn(fsig(lo), fsig(hi));
    }
    uint4* Eo = reinterpret_cast<uint4*>(g_Eh + (size_t)p*32);
    const uint4* ov = reinterpret_cast<const uint4*>(o);
    Eo[0] = ov[0]; Eo[1] = ov[1]; Eo[2] = ov[2]; Eo[3] = ov[3];
}

// ---------------- aggregate (gather CSR, fp16, MLP4) + node MLP ----------------
__device__ __forceinline__ float ldE(int entry, int b, int lane) {
    int row = ((entry >> 1) << 3) | b;
    float v = __half2float(__ldg(&g_Eh[(size_t)row*32 + lane]));
    return (entry & 1) ? -v : v;
}

__global__ void __launch_bounds__(256) k_agg_node(const float* __restrict__ Wn,
                                                  const float* __restrict__ bn,
                                                  float* __restrict__ out) {
    __shared__ float Wns[EOUT*NOUT];  // 30x64
    __shared__ float bns[NOUT];
    __shared__ float sA[8][33];
    for (int idx = threadIdx.x; idx < EOUT*NOUT; idx += blockDim.x) Wns[idx] = Wn[idx];
    if (threadIdx.x < NOUT) bns[threadIdx.x] = bn[threadIdx.x];
    __syncthreads();

    int warpId = threadIdx.x >> 5, lane = threadIdx.x & 31;
    int n = blockIdx.x;   // block = node, warp = batch (CSR list shared in L1)
    int b = warpId;
    int beg = g_off[n], end = g_off[n+1];

    float acc = 0.f;
    int i = beg;
    for (; i + 4 <= end; i += 4) {
        int e0 = __ldg(&g_list[i+0]);
        int e1 = __ldg(&g_list[i+1]);
        int e2 = __ldg(&g_list[i+2]);
        int e3 = __ldg(&g_list[i+3]);
        float v0 = ldE(e0, b, lane);
        float v1 = ldE(e1, b, lane);
        float v2 = ldE(e2, b, lane);
        float v3 = ldE(e3, b, lane);
        acc += (v0 + v1) + (v2 + v3);
    }
    for (; i < end; i++) acc += ldE(__ldg(&g_list[i]), b, lane);

    sA[warpId][lane] = (lane < EOUT) ? acc : 0.f;
    __syncwarp();

    float o0 = bns[lane], o1 = bns[lane + 32];
    #pragma unroll
    for (int j = 0; j < EOUT; j++) {
        float a = sA[warpId][j];
        o0 += a * Wns[j*NOUT + lane];
        o1 += a * Wns[j*NOUT + lane + 32];
    }
    int ob = ((b*NN + n) << 6) + lane;
    out[ob]      = fsig(o0);
    out[ob + 32] = fsig(o1);
}

// ---------------- launcher ----------------
extern "C" void kernel_launch(void* const* d_in, const int* in_sizes, int n_in,
                              void* d_out, int out_size) {
    const float* x  = (const float*)d_in[0];
    const int*   ei = (const int*)  d_in[1];
    const float* ea = (const float*)d_in[2];
    const float* wm = (const float*)d_in[3];
    const float* ws = (const float*)d_in[4];
    const float* W1 = (const float*)d_in[5];
    const float* b1 = (const float*)d_in[6];
    const float* W2 = (const float*)d_in[7];
    const float* b2 = (const float*)d_in[8];
    const float* Wn = (const float*)d_in[9];
    const float* bn = (const float*)d_in[10];
    float* out = (float*)d_out;

    k_stats_partial<<<256, 256>>>(ea);
    k_stats_final<<<1, 256>>>();
    k_node_pre<<<(NB + 255)/256, 256>>>(x, W1, wm, ws);
    k_edge_pre<<<(EE + 255)/256, 256>>>(ea, W1, b1);
    k_zero_cnt<<<(NN + 255)/256, 256>>>();
    k_hist<<<(EE + 255)/256, 256>>>(ei);
    k_scan<<<1, 1024>>>();
    k_scatter<<<(EE + 255)/256, 256>>>(ei);
    k_edge_main<<<PE/256, 256>>>(ei, W1, W2, b2);
    k_agg_node<<<NN, 256>>>(Wn, bn, out);
}

// round 4
// speedup vs baseline: 1.4383x; 1.3179x over previous
#include <cuda_runtime.h>
#include <cuda_fp16.h>
#include <cuda_bf16.h>
#include <math.h>

#define BB 8
#define NN 10000
#define DD 16
#define EE 320000
#define EH 32
#define EOUT 30
#define NOUT 64
#define NB (NN*BB)            // 80000 (b,n) pairs
#define PE (BB*EE)            // 2,560,000 (b,e) pairs

typedef unsigned long long ull;

// ---------------- device scratch ----------------
__device__ __align__(16) __half g_Ph[NB*32];      // x@W1[0:16] fp16, [n][b][32]
__device__ __align__(16) __half g_Qh[NB*32];      // x@W1[16:32] fp16
__device__ __align__(16) float2 g_SD[NB];         // (speed, direc) per (n,b)
__device__ __align__(16) __half g_Eh[(size_t)PE*32]; // e outputs fp16, [e][b][32]
__device__ double g_part[256*4];
__device__ float g_stats[4];                       // mean0, invstd0, mean1, invstd1
__device__ int g_cnt[NN];
__device__ int g_off[NN+1];
__device__ int g_cursor[NN];
__device__ int g_list[2*EE];                       // signed CSR entries: (e<<1)|is_src

// accurate sigmoid (MUFU ex2+rcp, rel err ~1e-6)
__device__ __forceinline__ float fsig(float x) {
    return __fdividef(1.0f, 1.0f + __expf(-x));
}
// fast sigmoid via HW tanh (hidden layer only; error attenuated by W2)
__device__ __forceinline__ float fsig_fast(float x) {
    float t;
    asm("tanh.approx.f32 %0, %1;" : "=f"(t) : "f"(x * 0.5f));
    return fmaf(t, 0.5f, 0.5f);
}

#define FMA_F32X2(d, a, b, c) \
    asm("fma.rn.f32x2 %0, %1, %2, %3;" : "=l"(d) : "l"(a), "l"(b), "l"(c))

__device__ __forceinline__ ull pack2(float lo, float hi) {
    ull r; asm("mov.b64 %0, {%1, %2};" : "=l"(r) : "f"(lo), "f"(hi)); return r;
}
__device__ __forceinline__ void unpack2(float& lo, float& hi, ull v) {
    asm("mov.b64 {%0, %1}, %2;" : "=f"(lo), "=f"(hi) : "l"(v));
}

// ---------------- stats pass 1 (+ zero g_cnt, saves a launch) ----------------
__global__ void k_stats_partial(const float* __restrict__ ea) {
    __shared__ double sm[256][4];
    int gtid = blockIdx.x*blockDim.x + threadIdx.x;
    if (gtid < NN) g_cnt[gtid] = 0;
    double a0=0, a1=0, a2=0, a3=0;
    for (int i = gtid; i < EE; i += gridDim.x*blockDim.x) {
        float2 v = reinterpret_cast<const float2*>(ea)[i];
        a0 += (double)v.x; a1 += (double)v.x*(double)v.x;
        a2 += (double)v.y; a3 += (double)v.y*(double)v.y;
    }
    int tid = threadIdx.x;
    sm[tid][0]=a0; sm[tid][1]=a1; sm[tid][2]=a2; sm[tid][3]=a3;
    __syncthreads();
    for (int s = 128; s > 0; s >>= 1) {
        if (tid < s) {
            sm[tid][0]+=sm[tid+s][0]; sm[tid][1]+=sm[tid+s][1];
            sm[tid][2]+=sm[tid+s][2]; sm[tid][3]+=sm[tid+s][3];
        }
        __syncthreads();
    }
    if (tid == 0) {
        g_part[blockIdx.x*4+0]=sm[0][0]; g_part[blockIdx.x*4+1]=sm[0][1];
        g_part[blockIdx.x*4+2]=sm[0][2]; g_part[blockIdx.x*4+3]=sm[0][3];
    }
}

// ---------------- stats pass 2 ----------------
__global__ void k_stats_final() {
    __shared__ double sm[256][4];
    int tid = threadIdx.x;
    sm[tid][0]=g_part[tid*4+0]; sm[tid][1]=g_part[tid*4+1];
    sm[tid][2]=g_part[tid*4+2]; sm[tid][3]=g_part[tid*4+3];
    __syncthreads();
    for (int s = 128; s > 0; s >>= 1) {
        if (tid < s) {
            sm[tid][0]+=sm[tid+s][0]; sm[tid][1]+=sm[tid+s][1];
            sm[tid][2]+=sm[tid+s][2]; sm[tid][3]+=sm[tid+s][3];
        }
        __syncthreads();
    }
    if (tid == 0) {
        double s0=sm[0][0], q0=sm[0][1], s1=sm[0][2], q1=sm[0][3];
        double m0 = s0/(double)EE;
        double m1 = s1/(double)EE;
        double v0 = (q0 - s0*s0/(double)EE) / (double)(EE-1);
        double v1 = (q1 - s1*s1/(double)EE) / (double)(EE-1);
        g_stats[0]=(float)m0; g_stats[1]=(float)(1.0/sqrt(v0));
        g_stats[2]=(float)m1; g_stats[3]=(float)(1.0/sqrt(v1));
    }
}

// ---------------- per-(b,n) precompute: P, Q (fp16), speed/direc ----------------
__global__ void k_node_pre(const float* __restrict__ x, const float* __restrict__ W1,
                           const float* __restrict__ wm, const float* __restrict__ ws) {
    __shared__ float W1s[32*32];
    for (int idx = threadIdx.x; idx < 32*32; idx += blockDim.x) W1s[idx] = W1[idx];
    __syncthreads();
    int pair = blockIdx.x*blockDim.x + threadIdx.x;
    if (pair >= NB) return;
    int n = pair >> 3, b = pair & 7;
    const float4* xr = reinterpret_cast<const float4*>(x + ((size_t)b*NN + n)*DD);
    float xv[16];
    #pragma unroll
    for (int d4 = 0; d4 < 4; d4++) {
        float4 v = xr[d4];
        xv[d4*4+0]=v.x; xv[d4*4+1]=v.y; xv[d4*4+2]=v.z; xv[d4*4+3]=v.w;
    }
    __align__(16) __half2 Pt[16], Qt[16];
    #pragma unroll
    for (int j2 = 0; j2 < 16; j2++) {
        float p0=0.f, p1=0.f, q0=0.f, q1=0.f;
        #pragma unroll
        for (int d = 0; d < 16; d++) {
            p0 += xv[d]*W1s[d*32 + j2*2];
            p1 += xv[d]*W1s[d*32 + j2*2 + 1];
            q0 += xv[d]*W1s[(16+d)*32 + j2*2];
            q1 += xv[d]*W1s[(16+d)*32 + j2*2 + 1];
        }
        Pt[j2] = __floats2half2_rn(p0, p1);
        Qt[j2] = __floats2half2_rn(q0, q1);
    }
    uint4* Po = reinterpret_cast<uint4*>(g_Ph + pair*32);
    uint4* Qo = reinterpret_cast<uint4*>(g_Qh + pair*32);
    const uint4* Pv = reinterpret_cast<const uint4*>(Pt);
    const uint4* Qv = reinterpret_cast<const uint4*>(Qt);
    #pragma unroll
    for (int i = 0; i < 4; i++) { Po[i] = Pv[i]; Qo[i] = Qv[i]; }
    g_SD[pair] = make_float2(xv[14]*ws[0] + wm[0], xv[15]*ws[1] + wm[1]);
}

// ---------------- CSR build ----------------
__global__ void k_hist(const int* __restrict__ ei) {
    int e = blockIdx.x*blockDim.x + threadIdx.x;
    if (e >= EE) return;
    atomicAdd(&g_cnt[ei[EE + e]], 1);
    atomicAdd(&g_cnt[ei[e]], 1);
}
__global__ void k_scan() {
    __shared__ int wsum[32];
    __shared__ int sbase_s;
    int tid = threadIdx.x, lane = tid & 31, w = tid >> 5;
    if (tid == 0) sbase_s = 0;
    __syncthreads();
    for (int start = 0; start < NN; start += 1024) {
        int i = start + tid;
        int v = (i < NN) ? g_cnt[i] : 0;
        int s = v;
        #pragma unroll
        for (int d = 1; d < 32; d <<= 1) {
            int t = __shfl_up_sync(0xFFFFFFFFu, s, d);
            if (lane >= d) s += t;
        }
        if (lane == 31) wsum[w] = s;
        __syncthreads();
        if (w == 0) {
            int ws = wsum[lane];
            #pragma unroll
            for (int d = 1; d < 32; d <<= 1) {
                int t = __shfl_up_sync(0xFFFFFFFFu, ws, d);
                if (lane >= d) ws += t;
            }
            wsum[lane] = ws;
        }
        __syncthreads();
        int base = sbase_s;
        int excl = base + s - v + (w > 0 ? wsum[w-1] : 0);
        if (i < NN) { g_off[i] = excl; g_cursor[i] = excl; }
        int total = wsum[31];
        __syncthreads();
        if (tid == 0) sbase_s = base + total;
        __syncthreads();
    }
    if (tid == 0) g_off[NN] = sbase_s;
}
__global__ void k_scatter(const int* __restrict__ ei) {
    int e = blockIdx.x*blockDim.x + threadIdx.x;
    if (e >= EE) return;
    int p1 = atomicAdd(&g_cursor[ei[EE + e]], 1);
    g_list[p1] = (e << 1);           // tgt: +e
    int p2 = atomicAdd(&g_cursor[ei[e]], 1);
    g_list[p2] = (e << 1) | 1;       // src: -e
}

// ---------------- fused per-(b,e) edge MLP (edge_pre folded in) ----------------
__global__ void __launch_bounds__(256) k_edge_main(const int* __restrict__ ei,
                                                   const float* __restrict__ ea,
                                                   const float* __restrict__ W1,
                                                   const float* __restrict__ b1,
                                                   const float* __restrict__ W2,
                                                   const float* __restrict__ b2) {
    __shared__ __align__(16) float W2s[32*32];   // [j][k], k padded to 32
    __shared__ __align__(16) float b2s[32];
    __shared__ float wA[32], wB[32], w1ds[32], b1s[32];
    __shared__ float st[4];
    for (int idx = threadIdx.x; idx < 32*32; idx += blockDim.x) {
        int j = idx >> 5, k = idx & 31;
        W2s[idx] = (k < EOUT) ? W2[j*EOUT + k] : 0.f;
    }
    if (threadIdx.x < 32) {
        wA[threadIdx.x]   = W1[32*32 + threadIdx.x];
        wB[threadIdx.x]   = W1[33*32 + threadIdx.x];
        w1ds[threadIdx.x] = W1[34*32 + threadIdx.x];
        b1s[threadIdx.x]  = b1[threadIdx.x];
        b2s[threadIdx.x]  = (threadIdx.x < EOUT) ? b2[threadIdx.x] : 0.f;
    }
    if (threadIdx.x >= 32 && threadIdx.x < 36) st[threadIdx.x-32] = g_stats[threadIdx.x-32];
    __syncthreads();

    int p = blockIdx.x*blockDim.x + threadIdx.x;
    if (p >= PE) return;
    int e = p >> 3, b = p & 7;
    int s = ei[e], t = ei[EE + e];
    int sp = (s << 3) | b, tp = (t << 3) | b;

    float2 eav = reinterpret_cast<const float2*>(ea)[e];   // broadcast across 8 b-threads
    float2 sd  = g_SD[sp];
    float ew = __fdividef(3.0f * sd.x * cosf(eav.y - sd.y), eav.x);
    ew = fmaxf(ew, 0.f);
    float a0 = (eav.x - st[0]) * st[1];
    float a1 = (eav.y - st[2]) * st[3];

    ull acc2[16];
    const ull* b2p = reinterpret_cast<const ull*>(b2s);
    #pragma unroll
    for (int k2 = 0; k2 < 16; k2++) acc2[k2] = b2p[k2];

    const uint4* Pr = reinterpret_cast<const uint4*>(g_Ph + sp*32);
    const uint4* Qr = reinterpret_cast<const uint4*>(g_Qh + tp*32);

    #pragma unroll
    for (int j8 = 0; j8 < 4; j8++) {
        uint4 pv4 = Pr[j8], qv4 = Qr[j8];
        const __half2* ph = reinterpret_cast<const __half2*>(&pv4);
        const __half2* qh = reinterpret_cast<const __half2*>(&qv4);
        #pragma unroll
        for (int j2 = 0; j2 < 4; j2++) {
            int j = j8*8 + j2*2;
            float2 pf = __half22float2(ph[j2]);
            float2 qf = __half22float2(qh[j2]);
            float z0 = pf.x + qf.x + b1s[j];
            z0 = fmaf(a0, wA[j],   z0);
            z0 = fmaf(a1, wB[j],   z0);
            z0 = fmaf(ew, w1ds[j], z0);
            float z1 = pf.y + qf.y + b1s[j+1];
            z1 = fmaf(a0, wA[j+1],   z1);
            z1 = fmaf(a1, wB[j+1],   z1);
            z1 = fmaf(ew, w1ds[j+1], z1);
            float h0 = fsig_fast(z0);
            float h1 = fsig_fast(z1);
            ull hd0 = pack2(h0, h0);
            ull hd1 = pack2(h1, h1);
            const ulonglong2* w0 = reinterpret_cast<const ulonglong2*>(&W2s[j*32]);
            const ulonglong2* w1 = reinterpret_cast<const ulonglong2*>(&W2s[(j+1)*32]);
            #pragma unroll
            for (int k4 = 0; k4 < 8; k4++) {
                ulonglong2 wv0 = w0[k4];
                ulonglong2 wv1 = w1[k4];
                FMA_F32X2(acc2[k4*2+0], hd0, wv0.x, acc2[k4*2+0]);
                FMA_F32X2(acc2[k4*2+1], hd0, wv0.y, acc2[k4*2+1]);
                FMA_F32X2(acc2[k4*2+0], hd1, wv1.x, acc2[k4*2+0]);
                FMA_F32X2(acc2[k4*2+1], hd1, wv1.y, acc2[k4*2+1]);
            }
        }
    }
    // accurate sigmoid + fp16 pack + 64 B store
    __align__(16) __half2 o[16];
    #pragma unroll
    for (int k2 = 0; k2 < 16; k2++) {
        float lo, hi; unpack2(lo, hi, acc2[k2]);
        o[k2] = __floats2half2_rn(fsig(lo), fsig(hi));
    }
    uint4* Eo = reinterpret_cast<uint4*>(g_Eh + (size_t)p*32);
    const uint4* ov = reinterpret_cast<const uint4*>(o);
    Eo[0] = ov[0]; Eo[1] = ov[1]; Eo[2] = ov[2]; Eo[3] = ov[3];
}

// ---------------- aggregate (gather CSR, fp16, MLP8) + node MLP ----------------
__device__ __forceinline__ float ldE(int entry, int b, int lane) {
    int row = ((entry >> 1) << 3) | b;
    float v = __half2float(__ldg(&g_Eh[(size_t)row*32 + lane]));
    return (entry & 1) ? -v : v;
}

__global__ void __launch_bounds__(256) k_agg_node(const float* __restrict__ Wn,
                                                  const float* __restrict__ bn,
                                                  float* __restrict__ out) {
    __shared__ float Wns[EOUT*NOUT];  // 30x64
    __shared__ float bns[NOUT];
    __shared__ float sA[8][33];
    for (int idx = threadIdx.x; idx < EOUT*NOUT; idx += blockDim.x) Wns[idx] = Wn[idx];
    if (threadIdx.x < NOUT) bns[threadIdx.x] = bn[threadIdx.x];
    __syncthreads();

    int warpId = threadIdx.x >> 5, lane = threadIdx.x & 31;
    int n = blockIdx.x;   // block = node, warp = batch (CSR list shared in L1)
    int b = warpId;
    int beg = g_off[n], end = g_off[n+1];

    float acc = 0.f;
    int i = beg;
    for (; i + 8 <= end; i += 8) {
        int en[8];
        #pragma unroll
        for (int u = 0; u < 8; u++) en[u] = __ldg(&g_list[i+u]);
        float v[8];
        #pragma unroll
        for (int u = 0; u < 8; u++) v[u] = ldE(en[u], b, lane);
        acc += ((v[0]+v[1]) + (v[2]+v[3])) + ((v[4]+v[5]) + (v[6]+v[7]));
    }
    for (; i < end; i++) acc += ldE(__ldg(&g_list[i]), b, lane);

    sA[warpId][lane] = (lane < EOUT) ? acc : 0.f;
    __syncwarp();

    float o0 = bns[lane], o1 = bns[lane + 32];
    #pragma unroll
    for (int j = 0; j < EOUT; j++) {
        float a = sA[warpId][j];
        o0 += a * Wns[j*NOUT + lane];
        o1 += a * Wns[j*NOUT + lane + 32];
    }
    int ob = ((b*NN + n) << 6) + lane;
    out[ob]      = fsig(o0);
    out[ob + 32] = fsig(o1);
}

// ---------------- launcher ----------------
extern "C" void kernel_launch(void* const* d_in, const int* in_sizes, int n_in,
                              void* d_out, int out_size) {
    const float* x  = (const float*)d_in[0];
    const int*   ei = (const int*)  d_in[1];
    const float* ea = (const float*)d_in[2];
    const float* wm = (const float*)d_in[3];
    const float* ws = (const float*)d_in[4];
    const float* W1 = (const float*)d_in[5];
    const float* b1 = (const float*)d_in[6];
    const float* W2 = (const float*)d_in[7];
    const float* b2 = (const float*)d_in[8];
    const float* Wn = (const float*)d_in[9];
    const float* bn = (const float*)d_in[10];
    float* out = (float*)d_out;

    k_stats_partial<<<256, 256>>>(ea);        // launch 0 (+ zeroes g_cnt)
    k_stats_final<<<1, 256>>>();              // launch 1
    k_node_pre<<<(NB + 255)/256, 256>>>(x, W1, wm, ws);   // launch 2
    k_edge_main<<<PE/256, 256>>>(ei, ea, W1, b1, W2, b2); // launch 3 (profiled slot)
    k_hist<<<(EE + 255)/256, 256>>>(ei);      // launch 4
    k_scan<<<1, 1024>>>();                    // launch 5
    k_scatter<<<(EE + 255)/256, 256>>>(ei);   // launch 6
    k_agg_node<<<NN, 256>>>(Wn, bn, out);     // launch 7
}

// round 5
// speedup vs baseline: 1.5483x; 1.0765x over previous
#include <cuda_runtime.h>
#include <cuda_fp16.h>
#include <cuda_bf16.h>
#include <math.h>

#define BB 8
#define NN 10000
#define DD 16
#define EE 320000
#define EH 32
#define EOUT 30
#define NOUT 64
#define NB (NN*BB)            // 80000 (b,n) pairs
#define PE (BB*EE)            // 2,560,000 (b,e) pairs

typedef unsigned long long ull;

// ---------------- device scratch ----------------
__device__ __align__(16) __half g_Ph[NB*32];      // x@W1[0:16] fp16, [n][b][32]
__device__ __align__(16) __half g_Qh[NB*32];      // x@W1[16:32] fp16
__device__ __align__(16) float2 g_SD[NB];         // (speed, direc) per (n,b)
__device__ __align__(16) __half g_Eh[(size_t)PE*32]; // e outputs fp16, [e][b][32]
__device__ double g_part[256*4];
__device__ float g_stats[4];                       // mean0, invstd0, mean1, invstd1
__device__ int g_cnt[NN];
__device__ int g_off[NN+1];
__device__ int g_cursor[NN];
__device__ int g_list[2*EE];                       // signed CSR entries: (e<<1)|is_src

// accurate sigmoid (MUFU ex2+rcp, rel err ~1e-6) -- used for final output only
__device__ __forceinline__ float fsig(float x) {
    return __fdividef(1.0f, 1.0f + __expf(-x));
}
// fast sigmoid via HW tanh (1 MUFU)
__device__ __forceinline__ float fsig_fast(float x) {
    float t;
    asm("tanh.approx.f32 %0, %1;" : "=f"(t) : "f"(x * 0.5f));
    return fmaf(t, 0.5f, 0.5f);
}

#define FMA_F32X2(d, a, b, c) \
    asm("fma.rn.f32x2 %0, %1, %2, %3;" : "=l"(d) : "l"(a), "l"(b), "l"(c))

__device__ __forceinline__ ull pack2(float lo, float hi) {
    ull r; asm("mov.b64 %0, {%1, %2};" : "=l"(r) : "f"(lo), "f"(hi)); return r;
}
__device__ __forceinline__ void unpack2(float& lo, float& hi, ull v) {
    asm("mov.b64 {%0, %1}, %2;" : "=f"(lo), "=f"(hi) : "l"(v));
}

// ---------------- stats pass 1 (+ zero g_cnt) ----------------
__global__ void k_stats_partial(const float* __restrict__ ea) {
    __shared__ double sm[256][4];
    int gtid = blockIdx.x*blockDim.x + threadIdx.x;
    if (gtid < NN) g_cnt[gtid] = 0;
    double a0=0, a1=0, a2=0, a3=0;
    for (int i = gtid; i < EE; i += gridDim.x*blockDim.x) {
        float2 v = reinterpret_cast<const float2*>(ea)[i];
        a0 += (double)v.x; a1 += (double)v.x*(double)v.x;
        a2 += (double)v.y; a3 += (double)v.y*(double)v.y;
    }
    int tid = threadIdx.x;
    sm[tid][0]=a0; sm[tid][1]=a1; sm[tid][2]=a2; sm[tid][3]=a3;
    __syncthreads();
    for (int s = 128; s > 0; s >>= 1) {
        if (tid < s) {
            sm[tid][0]+=sm[tid+s][0]; sm[tid][1]+=sm[tid+s][1];
            sm[tid][2]+=sm[tid+s][2]; sm[tid][3]+=sm[tid+s][3];
        }
        __syncthreads();
    }
    if (tid == 0) {
        g_part[blockIdx.x*4+0]=sm[0][0]; g_part[blockIdx.x*4+1]=sm[0][1];
        g_part[blockIdx.x*4+2]=sm[0][2]; g_part[blockIdx.x*4+3]=sm[0][3];
    }
}

// ---------------- stats pass 2 ----------------
__global__ void k_stats_final() {
    __shared__ double sm[256][4];
    int tid = threadIdx.x;
    sm[tid][0]=g_part[tid*4+0]; sm[tid][1]=g_part[tid*4+1];
    sm[tid][2]=g_part[tid*4+2]; sm[tid][3]=g_part[tid*4+3];
    __syncthreads();
    for (int s = 128; s > 0; s >>= 1) {
        if (tid < s) {
            sm[tid][0]+=sm[tid+s][0]; sm[tid][1]+=sm[tid+s][1];
            sm[tid][2]+=sm[tid+s][2]; sm[tid][3]+=sm[tid+s][3];
        }
        __syncthreads();
    }
    if (tid == 0) {
        double s0=sm[0][0], q0=sm[0][1], s1=sm[0][2], q1=sm[0][3];
        double m0 = s0/(double)EE;
        double m1 = s1/(double)EE;
        double v0 = (q0 - s0*s0/(double)EE) / (double)(EE-1);
        double v1 = (q1 - s1*s1/(double)EE) / (double)(EE-1);
        g_stats[0]=(float)m0; g_stats[1]=(float)(1.0/sqrt(v0));
        g_stats[2]=(float)m1; g_stats[3]=(float)(1.0/sqrt(v1));
    }
}

// ---------------- per-(b,n) precompute: P, Q (fp16), speed/direc ----------------
__global__ void k_node_pre(const float* __restrict__ x, const float* __restrict__ W1,
                           const float* __restrict__ wm, const float* __restrict__ ws) {
    __shared__ float W1s[32*32];
    for (int idx = threadIdx.x; idx < 32*32; idx += blockDim.x) W1s[idx] = W1[idx];
    __syncthreads();
    int pair = blockIdx.x*blockDim.x + threadIdx.x;
    if (pair >= NB) return;
    int n = pair >> 3, b = pair & 7;
    const float4* xr = reinterpret_cast<const float4*>(x + ((size_t)b*NN + n)*DD);
    float xv[16];
    #pragma unroll
    for (int d4 = 0; d4 < 4; d4++) {
        float4 v = xr[d4];
        xv[d4*4+0]=v.x; xv[d4*4+1]=v.y; xv[d4*4+2]=v.z; xv[d4*4+3]=v.w;
    }
    __align__(16) __half2 Pt[16], Qt[16];
    #pragma unroll
    for (int j2 = 0; j2 < 16; j2++) {
        float p0=0.f, p1=0.f, q0=0.f, q1=0.f;
        #pragma unroll
        for (int d = 0; d < 16; d++) {
            p0 += xv[d]*W1s[d*32 + j2*2];
            p1 += xv[d]*W1s[d*32 + j2*2 + 1];
            q0 += xv[d]*W1s[(16+d)*32 + j2*2];
            q1 += xv[d]*W1s[(16+d)*32 + j2*2 + 1];
        }
        Pt[j2] = __floats2half2_rn(p0, p1);
        Qt[j2] = __floats2half2_rn(q0, q1);
    }
    uint4* Po = reinterpret_cast<uint4*>(g_Ph + pair*32);
    uint4* Qo = reinterpret_cast<uint4*>(g_Qh + pair*32);
    const uint4* Pv = reinterpret_cast<const uint4*>(Pt);
    const uint4* Qv = reinterpret_cast<const uint4*>(Qt);
    #pragma unroll
    for (int i = 0; i < 4; i++) { Po[i] = Pv[i]; Qo[i] = Qv[i]; }
    g_SD[pair] = make_float2(xv[14]*ws[0] + wm[0], xv[15]*ws[1] + wm[1]);
}

// ---------------- CSR build ----------------
__global__ void k_hist(const int* __restrict__ ei) {
    int e = blockIdx.x*blockDim.x + threadIdx.x;
    if (e >= EE) return;
    atomicAdd(&g_cnt[ei[EE + e]], 1);
    atomicAdd(&g_cnt[ei[e]], 1);
}
__global__ void k_scan() {
    __shared__ int wsum[32];
    __shared__ int sbase_s;
    int tid = threadIdx.x, lane = tid & 31, w = tid >> 5;
    if (tid == 0) sbase_s = 0;
    __syncthreads();
    for (int start = 0; start < NN; start += 1024) {
        int i = start + tid;
        int v = (i < NN) ? g_cnt[i] : 0;
        int s = v;
        #pragma unroll
        for (int d = 1; d < 32; d <<= 1) {
            int t = __shfl_up_sync(0xFFFFFFFFu, s, d);
            if (lane >= d) s += t;
        }
        if (lane == 31) wsum[w] = s;
        __syncthreads();
        if (w == 0) {
            int ws = wsum[lane];
            #pragma unroll
            for (int d = 1; d < 32; d <<= 1) {
                int t = __shfl_up_sync(0xFFFFFFFFu, ws, d);
                if (lane >= d) ws += t;
            }
            wsum[lane] = ws;
        }
        __syncthreads();
        int base = sbase_s;
        int excl = base + s - v + (w > 0 ? wsum[w-1] : 0);
        if (i < NN) { g_off[i] = excl; g_cursor[i] = excl; }
        int total = wsum[31];
        __syncthreads();
        if (tid == 0) sbase_s = base + total;
        __syncthreads();
    }
    if (tid == 0) g_off[NN] = sbase_s;
}
__global__ void k_scatter(const int* __restrict__ ei) {
    int e = blockIdx.x*blockDim.x + threadIdx.x;
    if (e >= EE) return;
    int p1 = atomicAdd(&g_cursor[ei[EE + e]], 1);
    g_list[p1] = (e << 1);           // tgt: +e
    int p2 = atomicAdd(&g_cursor[ei[e]], 1);
    g_list[p2] = (e << 1) | 1;       // src: -e
}

// ---------------- fused edge MLP, ILP-2 over batch pairs ----------------
// Each thread handles (e, b0=2u) and (e, b0+1): W2 smem reads amortized 2x.
__global__ void __launch_bounds__(256, 2) k_edge_main(const int* __restrict__ ei,
                                                      const float* __restrict__ ea,
                                                      const float* __restrict__ W1,
                                                      const float* __restrict__ b1,
                                                      const float* __restrict__ W2,
                                                      const float* __restrict__ b2) {
    __shared__ __align__(16) float W2s[32*32];   // [j][k], k padded to 32
    __shared__ __align__(16) float b2s[32];
    __shared__ float wA[32], wB[32], w1ds[32], b1s[32];
    __shared__ float st[4];
    for (int idx = threadIdx.x; idx < 32*32; idx += blockDim.x) {
        int j = idx >> 5, k = idx & 31;
        W2s[idx] = (k < EOUT) ? W2[j*EOUT + k] : 0.f;
    }
    if (threadIdx.x < 32) {
        wA[threadIdx.x]   = W1[32*32 + threadIdx.x];
        wB[threadIdx.x]   = W1[33*32 + threadIdx.x];
        w1ds[threadIdx.x] = W1[34*32 + threadIdx.x];
        b1s[threadIdx.x]  = b1[threadIdx.x];
        b2s[threadIdx.x]  = (threadIdx.x < EOUT) ? b2[threadIdx.x] : 0.f;
    }
    if (threadIdx.x >= 32 && threadIdx.x < 36) st[threadIdx.x-32] = g_stats[threadIdx.x-32];
    __syncthreads();

    int p = blockIdx.x*blockDim.x + threadIdx.x;   // p in [0, PE/2)
    if (p >= PE/2) return;
    int e = p >> 2, u = p & 3;
    int b0 = u << 1;
    int s = ei[e], t = ei[EE + e];
    int sp = (s << 3) | b0, tp = (t << 3) | b0;    // item B rows are sp+1 / tp+1

    float2 eav = reinterpret_cast<const float2*>(ea)[e];
    float2 sd0 = g_SD[sp], sd1 = g_SD[sp+1];
    float inv_d = __fdividef(3.0f, eav.x);
    float ewA = fmaxf(inv_d * sd0.x * cosf(eav.y - sd0.y), 0.f);
    float ewB = fmaxf(inv_d * sd1.x * cosf(eav.y - sd1.y), 0.f);
    float a0 = (eav.x - st[0]) * st[1];
    float a1 = (eav.y - st[2]) * st[3];

    ull accA[16], accB[16];
    const ull* b2p = reinterpret_cast<const ull*>(b2s);
    #pragma unroll
    for (int k2 = 0; k2 < 16; k2++) { accA[k2] = b2p[k2]; accB[k2] = b2p[k2]; }

    const uint4* PrA = reinterpret_cast<const uint4*>(g_Ph) + (size_t)sp*4;
    const uint4* QrA = reinterpret_cast<const uint4*>(g_Qh) + (size_t)tp*4;
    const uint4* PrB = PrA + 4;
    const uint4* QrB = QrA + 4;

    #pragma unroll
    for (int j8 = 0; j8 < 4; j8++) {
        uint4 pA4 = PrA[j8], qA4 = QrA[j8], pB4 = PrB[j8], qB4 = QrB[j8];
        const __half2* phA = reinterpret_cast<const __half2*>(&pA4);
        const __half2* qhA = reinterpret_cast<const __half2*>(&qA4);
        const __half2* phB = reinterpret_cast<const __half2*>(&pB4);
        const __half2* qhB = reinterpret_cast<const __half2*>(&qB4);
        #pragma unroll
        for (int j2 = 0; j2 < 4; j2++) {
            int j = j8*8 + j2*2;
            float2 pfA = __half22float2(phA[j2]);
            float2 qfA = __half22float2(qhA[j2]);
            float2 pfB = __half22float2(phB[j2]);
            float2 qfB = __half22float2(qhB[j2]);
            // shared per-edge affine part
            float c0 = b1s[j];
            c0 = fmaf(a0, wA[j], c0);
            c0 = fmaf(a1, wB[j], c0);
            float c1 = b1s[j+1];
            c1 = fmaf(a0, wA[j+1], c1);
            c1 = fmaf(a1, wB[j+1], c1);
            float hA0 = fsig_fast(fmaf(ewA, w1ds[j],   pfA.x + qfA.x + c0));
            float hA1 = fsig_fast(fmaf(ewA, w1ds[j+1], pfA.y + qfA.y + c1));
            float hB0 = fsig_fast(fmaf(ewB, w1ds[j],   pfB.x + qfB.x + c0));
            float hB1 = fsig_fast(fmaf(ewB, w1ds[j+1], pfB.y + qfB.y + c1));
            ull hdA0 = pack2(hA0, hA0), hdA1 = pack2(hA1, hA1);
            ull hdB0 = pack2(hB0, hB0), hdB1 = pack2(hB1, hB1);
            const ulonglong2* w0 = reinterpret_cast<const ulonglong2*>(&W2s[j*32]);
            const ulonglong2* w1 = reinterpret_cast<const ulonglong2*>(&W2s[(j+1)*32]);
            #pragma unroll
            for (int k4 = 0; k4 < 8; k4++) {
                ulonglong2 wv0 = w0[k4];
                ulonglong2 wv1 = w1[k4];
                FMA_F32X2(accA[k4*2+0], hdA0, wv0.x, accA[k4*2+0]);
                FMA_F32X2(accA[k4*2+1], hdA0, wv0.y, accA[k4*2+1]);
                FMA_F32X2(accB[k4*2+0], hdB0, wv0.x, accB[k4*2+0]);
                FMA_F32X2(accB[k4*2+1], hdB0, wv0.y, accB[k4*2+1]);
                FMA_F32X2(accA[k4*2+0], hdA1, wv1.x, accA[k4*2+0]);
                FMA_F32X2(accA[k4*2+1], hdA1, wv1.y, accA[k4*2+1]);
                FMA_F32X2(accB[k4*2+0], hdB1, wv1.x, accB[k4*2+0]);
                FMA_F32X2(accB[k4*2+1], hdB1, wv1.y, accB[k4*2+1]);
            }
        }
    }
    // fast sigmoid + fp16 pack + 2x 64 B store (adjacent rows)
    __align__(16) __half2 oA[16], oB[16];
    #pragma unroll
    for (int k2 = 0; k2 < 16; k2++) {
        float lo, hi;
        unpack2(lo, hi, accA[k2]);
        oA[k2] = __floats2half2_rn(fsig_fast(lo), fsig_fast(hi));
        unpack2(lo, hi, accB[k2]);
        oB[k2] = __floats2half2_rn(fsig_fast(lo), fsig_fast(hi));
    }
    size_t row = (size_t)((e << 3) | b0) * 32;
    uint4* EoA = reinterpret_cast<uint4*>(g_Eh + row);
    uint4* EoB = reinterpret_cast<uint4*>(g_Eh + row + 32);
    const uint4* ovA = reinterpret_cast<const uint4*>(oA);
    const uint4* ovB = reinterpret_cast<const uint4*>(oB);
    #pragma unroll
    for (int i = 0; i < 4; i++) { EoA[i] = ovA[i]; EoB[i] = ovB[i]; }
}

// ---------------- aggregate (gather CSR, fp16, MLP8) + node MLP ----------------
__device__ __forceinline__ float ldE(int entry, int b, int lane) {
    int row = ((entry >> 1) << 3) | b;
    float v = __half2float(__ldg(&g_Eh[(size_t)row*32 + lane]));
    return (entry & 1) ? -v : v;
}

__global__ void __launch_bounds__(256) k_agg_node(const float* __restrict__ Wn,
                                                  const float* __restrict__ bn,
                                                  float* __restrict__ out) {
    __shared__ float Wns[EOUT*NOUT];  // 30x64
    __shared__ float bns[NOUT];
    __shared__ float sA[8][33];
    for (int idx = threadIdx.x; idx < EOUT*NOUT; idx += blockDim.x) Wns[idx] = Wn[idx];
    if (threadIdx.x < NOUT) bns[threadIdx.x] = bn[threadIdx.x];
    __syncthreads();

    int warpId = threadIdx.x >> 5, lane = threadIdx.x & 31;
    int n = blockIdx.x;   // block = node, warp = batch
    int b = warpId;
    int beg = g_off[n], end = g_off[n+1];

    float acc = 0.f;
    int i = beg;
    for (; i + 8 <= end; i += 8) {
        int en[8];
        #pragma unroll
        for (int u = 0; u < 8; u++) en[u] = __ldg(&g_list[i+u]);
        float v[8];
        #pragma unroll
        for (int u = 0; u < 8; u++) v[u] = ldE(en[u], b, lane);
        acc += ((v[0]+v[1]) + (v[2]+v[3])) + ((v[4]+v[5]) + (v[6]+v[7]));
    }
    for (; i < end; i++) acc += ldE(__ldg(&g_list[i]), b, lane);

    sA[warpId][lane] = (lane < EOUT) ? acc : 0.f;
    __syncwarp();

    float o0 = bns[lane], o1 = bns[lane + 32];
    #pragma unroll
    for (int j = 0; j < EOUT; j++) {
        float a = sA[warpId][j];
        o0 += a * Wns[j*NOUT + lane];
        o1 += a * Wns[j*NOUT + lane + 32];
    }
    int ob = ((b*NN + n) << 6) + lane;
    out[ob]      = fsig(o0);
    out[ob + 32] = fsig(o1);
}

// ---------------- launcher ----------------
extern "C" void kernel_launch(void* const* d_in, const int* in_sizes, int n_in,
                              void* d_out, int out_size) {
    const float* x  = (const float*)d_in[0];
    const int*   ei = (const int*)  d_in[1];
    const float* ea = (const float*)d_in[2];
    const float* wm = (const float*)d_in[3];
    const float* ws = (const float*)d_in[4];
    const float* W1 = (const float*)d_in[5];
    const float* b1 = (const float*)d_in[6];
    const float* W2 = (const float*)d_in[7];
    const float* b2 = (const float*)d_in[8];
    const float* Wn = (const float*)d_in[9];
    const float* bn = (const float*)d_in[10];
    float* out = (float*)d_out;

    k_stats_partial<<<256, 256>>>(ea);        // launch 0 (+ zeroes g_cnt)
    k_stats_final<<<1, 256>>>();              // launch 1
    k_node_pre<<<(NB + 255)/256, 256>>>(x, W1, wm, ws);       // launch 2
    k_edge_main<<<(PE/2)/256, 256>>>(ei, ea, W1, b1, W2, b2); // launch 3 (profiled)
    k_hist<<<(EE + 255)/256, 256>>>(ei);      // launch 4
    k_scan<<<1, 1024>>>();                    // launch 5
    k_scatter<<<(EE + 255)/256, 256>>>(ei);   // launch 6
    k_agg_node<<<NN, 256>>>(Wn, bn, out);     // launch 7
}

// round 7
// speedup vs baseline: 1.6843x; 1.0879x over previous
#include <cuda_runtime.h>
#include <cuda_fp16.h>
#include <cuda_bf16.h>
#include <math.h>

#define BB 8
#define NN 10000
#define DD 16
#define EE 320000
#define EH 32
#define EOUT 30
#define NOUT 64
#define NB (NN*BB)            // 80000 (b,n) pairs
#define PE (BB*EE)            // 2,560,000 (b,e) pairs

typedef unsigned long long ull;

// ---------------- device scratch ----------------
__device__ __align__(16) __half g_Ph[NB*32];      // x@W1[0:16] fp16, [n][b][32]
__device__ __align__(16) __half g_Qh[NB*32];      // x@W1[16:32] fp16
__device__ __align__(16) float2 g_SD[NB];         // (speed, direc) per (n,b)
__device__ __align__(16) __half g_Eh[(size_t)PE*32]; // e outputs fp16, [e][b][32]
__device__ double g_part[256*4];
__device__ float g_stats[4];                       // mean0, invstd0, mean1, invstd1
__device__ int g_cnt[NN];
__device__ int g_off[NN+1];
__device__ int g_cursor[NN];
__device__ int g_list[2*EE];                       // signed CSR entries: (e<<1)|is_src

__device__ __forceinline__ float fsig(float x) {
    return __fdividef(1.0f, 1.0f + __expf(-x));
}
__device__ __forceinline__ float fsig_fast(float x) {
    float t;
    asm("tanh.approx.f32 %0, %1;" : "=f"(t) : "f"(x * 0.5f));
    return fmaf(t, 0.5f, 0.5f);
}

#define FMA_F32X2(d, a, b, c) \
    asm("fma.rn.f32x2 %0, %1, %2, %3;" : "=l"(d) : "l"(a), "l"(b), "l"(c))

__device__ __forceinline__ ull pack2(float lo, float hi) {
    ull r; asm("mov.b64 %0, {%1, %2};" : "=l"(r) : "f"(lo), "f"(hi)); return r;
}
__device__ __forceinline__ void unpack2(float& lo, float& hi, ull v) {
    asm("mov.b64 {%0, %1}, %2;" : "=f"(lo), "=f"(hi) : "l"(v));
}

// ---------------- stats pass 1 (+ zero g_cnt) ----------------
__global__ void k_stats_partial(const float* __restrict__ ea) {
    __shared__ double sm[256][4];
    int gtid = blockIdx.x*blockDim.x + threadIdx.x;
    if (gtid < NN) g_cnt[gtid] = 0;
    double a0=0, a1=0, a2=0, a3=0;
    for (int i = gtid; i < EE; i += gridDim.x*blockDim.x) {
        float2 v = reinterpret_cast<const float2*>(ea)[i];
        a0 += (double)v.x; a1 += (double)v.x*(double)v.x;
        a2 += (double)v.y; a3 += (double)v.y*(double)v.y;
    }
    int tid = threadIdx.x;
    sm[tid][0]=a0; sm[tid][1]=a1; sm[tid][2]=a2; sm[tid][3]=a3;
    __syncthreads();
    for (int s = 128; s > 0; s >>= 1) {
        if (tid < s) {
            sm[tid][0]+=sm[tid+s][0]; sm[tid][1]+=sm[tid+s][1];
            sm[tid][2]+=sm[tid+s][2]; sm[tid][3]+=sm[tid+s][3];
        }
        __syncthreads();
    }
    if (tid == 0) {
        g_part[blockIdx.x*4+0]=sm[0][0]; g_part[blockIdx.x*4+1]=sm[0][1];
        g_part[blockIdx.x*4+2]=sm[0][2]; g_part[blockIdx.x*4+3]=sm[0][3];
    }
}

// ---------------- stats pass 2 ----------------
__global__ void k_stats_final() {
    __shared__ double sm[256][4];
    int tid = threadIdx.x;
    sm[tid][0]=g_part[tid*4+0]; sm[tid][1]=g_part[tid*4+1];
    sm[tid][2]=g_part[tid*4+2]; sm[tid][3]=g_part[tid*4+3];
    __syncthreads();
    for (int s = 128; s > 0; s >>= 1) {
        if (tid < s) {
            sm[tid][0]+=sm[tid+s][0]; sm[tid][1]+=sm[tid+s][1];
            sm[tid][2]+=sm[tid+s][2]; sm[tid][3]+=sm[tid+s][3];
        }
        __syncthreads();
    }
    if (tid == 0) {
        double s0=sm[0][0], q0=sm[0][1], s1=sm[0][2], q1=sm[0][3];
        double m0 = s0/(double)EE;
        double m1 = s1/(double)EE;
        double v0 = (q0 - s0*s0/(double)EE) / (double)(EE-1);
        double v1 = (q1 - s1*s1/(double)EE) / (double)(EE-1);
        g_stats[0]=(float)m0; g_stats[1]=(float)(1.0/sqrt(v0));
        g_stats[2]=(float)m1; g_stats[3]=(float)(1.0/sqrt(v1));
    }
}

// ---------------- per-(b,n) precompute: P, Q (fp16), speed/direc ----------------
__global__ void k_node_pre(const float* __restrict__ x, const float* __restrict__ W1,
                           const float* __restrict__ wm, const float* __restrict__ ws) {
    __shared__ float W1s[32*32];
    for (int idx = threadIdx.x; idx < 32*32; idx += blockDim.x) W1s[idx] = W1[idx];
    __syncthreads();
    int pair = blockIdx.x*blockDim.x + threadIdx.x;
    if (pair >= NB) return;
    int n = pair >> 3, b = pair & 7;
    const float4* xr = reinterpret_cast<const float4*>(x + ((size_t)b*NN + n)*DD);
    float xv[16];
    #pragma unroll
    for (int d4 = 0; d4 < 4; d4++) {
        float4 v = xr[d4];
        xv[d4*4+0]=v.x; xv[d4*4+1]=v.y; xv[d4*4+2]=v.z; xv[d4*4+3]=v.w;
    }
    __align__(16) __half2 Pt[16], Qt[16];
    #pragma unroll
    for (int j2 = 0; j2 < 16; j2++) {
        float p0=0.f, p1=0.f, q0=0.f, q1=0.f;
        #pragma unroll
        for (int d = 0; d < 16; d++) {
            p0 += xv[d]*W1s[d*32 + j2*2];
            p1 += xv[d]*W1s[d*32 + j2*2 + 1];
            q0 += xv[d]*W1s[(16+d)*32 + j2*2];
            q1 += xv[d]*W1s[(16+d)*32 + j2*2 + 1];
        }
        Pt[j2] = __floats2half2_rn(p0, p1);
        Qt[j2] = __floats2half2_rn(q0, q1);
    }
    uint4* Po = reinterpret_cast<uint4*>(g_Ph + pair*32);
    uint4* Qo = reinterpret_cast<uint4*>(g_Qh + pair*32);
    const uint4* Pv = reinterpret_cast<const uint4*>(Pt);
    const uint4* Qv = reinterpret_cast<const uint4*>(Qt);
    #pragma unroll
    for (int i = 0; i < 4; i++) { Po[i] = Pv[i]; Qo[i] = Qv[i]; }
    g_SD[pair] = make_float2(xv[14]*ws[0] + wm[0], xv[15]*ws[1] + wm[1]);
}

// ---------------- CSR build ----------------
__global__ void k_hist(const int* __restrict__ ei) {
    int e = blockIdx.x*blockDim.x + threadIdx.x;
    if (e >= EE) return;
    atomicAdd(&g_cnt[ei[EE + e]], 1);
    atomicAdd(&g_cnt[ei[e]], 1);
}
__global__ void k_scan() {
    __shared__ int wsum[32];
    __shared__ int sbase_s;
    int tid = threadIdx.x, lane = tid & 31, w = tid >> 5;
    if (tid == 0) sbase_s = 0;
    __syncthreads();
    for (int start = 0; start < NN; start += 1024) {
        int i = start + tid;
        int v = (i < NN) ? g_cnt[i] : 0;
        int s = v;
        #pragma unroll
        for (int d = 1; d < 32; d <<= 1) {
            int t = __shfl_up_sync(0xFFFFFFFFu, s, d);
            if (lane >= d) s += t;
        }
        if (lane == 31) wsum[w] = s;
        __syncthreads();
        if (w == 0) {
            int ws = wsum[lane];
            #pragma unroll
            for (int d = 1; d < 32; d <<= 1) {
                int t = __shfl_up_sync(0xFFFFFFFFu, ws, d);
                if (lane >= d) ws += t;
            }
            wsum[lane] = ws;
        }
        __syncthreads();
        int base = sbase_s;
        int excl = base + s - v + (w > 0 ? wsum[w-1] : 0);
        if (i < NN) { g_off[i] = excl; g_cursor[i] = excl; }
        int total = wsum[31];
        __syncthreads();
        if (tid == 0) sbase_s = base + total;
        __syncthreads();
    }
    if (tid == 0) g_off[NN] = sbase_s;
}
__global__ void k_scatter(const int* __restrict__ ei) {
    int e = blockIdx.x*blockDim.x + threadIdx.x;
    if (e >= EE) return;
    int p1 = atomicAdd(&g_cursor[ei[EE + e]], 1);
    g_list[p1] = (e << 1);           // tgt: +e
    int p2 = atomicAdd(&g_cursor[ei[e]], 1);
    g_list[p2] = (e << 1) | 1;       // src: -e
}

// ---------------- fused edge MLP: coalesced-staged P/Q + staged stores ----------------
// Block = 128 threads (4 warps). Each warp owns 8 consecutive edges (64 items).
// Per-warp 8.25KB smem buffer stages the 8 P-blocks + 8 Q-blocks (512B each,
// loaded fully coalesced), is consumed by the GEMM via smem, then is reused
// to stage the 4KB of outputs for a fully coalesced global write.
#define PQ_BLK 528            // 512 data + 16 pad bytes
#define PQ_WARP (16*PQ_BLK)   // 8448 B per warp
#define OUT_STRIDE 144        // 128 data + 16 pad, 16B-aligned

__global__ void __launch_bounds__(128) k_edge_main(const int* __restrict__ ei,
                                                   const float* __restrict__ ea,
                                                   const float* __restrict__ W1,
                                                   const float* __restrict__ b1,
                                                   const float* __restrict__ W2,
                                                   const float* __restrict__ b2) {
    __shared__ __align__(16) float W2s[32*32];   // [j][k], k padded to 32
    __shared__ __align__(16) float b2s[32];
    __shared__ float wA[32], wB[32], w1ds[32], b1s[32];
    __shared__ float st[4];
    __shared__ __align__(16) char PQ[4*PQ_WARP]; // 33792 B

    for (int idx = threadIdx.x; idx < 32*32; idx += blockDim.x) {
        int j = idx >> 5, k = idx & 31;
        W2s[idx] = (k < EOUT) ? W2[j*EOUT + k] : 0.f;
    }
    if (threadIdx.x < 32) {
        wA[threadIdx.x]   = W1[32*32 + threadIdx.x];
        wB[threadIdx.x]   = W1[33*32 + threadIdx.x];
        w1ds[threadIdx.x] = W1[34*32 + threadIdx.x];
        b1s[threadIdx.x]  = b1[threadIdx.x];
        b2s[threadIdx.x]  = (threadIdx.x < EOUT) ? b2[threadIdx.x] : 0.f;
    }
    if (threadIdx.x >= 32 && threadIdx.x < 36) st[threadIdx.x-32] = g_stats[threadIdx.x-32];
    __syncthreads();

    int w = threadIdx.x >> 5, lane = threadIdx.x & 31;
    int ebase = blockIdx.x*32 + w*8;
    char* wb = PQ + w*PQ_WARP;

    // ---- Stage 8 P-blocks (i=0..7) and 8 Q-blocks (i=8..15), coalesced ----
    #pragma unroll
    for (int i = 0; i < 16; i++) {
        int gi = i & 7;
        int nd = (i < 8) ? ei[ebase + gi] : ei[EE + ebase + gi];   // uniform -> broadcast
        const uint4* src = reinterpret_cast<const uint4*>(
            ((i < 8) ? g_Ph : g_Qh) + (size_t)nd*256);
        *reinterpret_cast<uint4*>(wb + i*PQ_BLK + lane*16) = src[lane];
    }
    __syncwarp();

    // ---- per-thread items: (e, b0) and (e, b0+1) ----
    int p  = blockIdx.x*128 + threadIdx.x;
    int e  = p >> 2;
    int gi = lane >> 2;
    int b0 = (lane & 3) << 1;
    int s  = ei[e];
    int sp = (s << 3) | b0;

    float2 eav = reinterpret_cast<const float2*>(ea)[e];
    float4 sd01 = *reinterpret_cast<const float4*>(&g_SD[sp]);  // sp even -> 16B aligned
    float inv_d = __fdividef(3.0f, eav.x);
    float ewA = fmaxf(inv_d * sd01.x * cosf(eav.y - sd01.y), 0.f);
    float ewB = fmaxf(inv_d * sd01.z * cosf(eav.y - sd01.w), 0.f);
    float a0 = (eav.x - st[0]) * st[1];
    float a1 = (eav.y - st[2]) * st[3];

    ull accA[16], accB[16];
    const ull* b2p = reinterpret_cast<const ull*>(b2s);
    #pragma unroll
    for (int k2 = 0; k2 < 16; k2++) { accA[k2] = b2p[k2]; accB[k2] = b2p[k2]; }

    const uint4* Pb = reinterpret_cast<const uint4*>(wb + gi*PQ_BLK + b0*64);
    const uint4* Qb = reinterpret_cast<const uint4*>(wb + (8+gi)*PQ_BLK + b0*64);

    #pragma unroll
    for (int j8 = 0; j8 < 4; j8++) {
        uint4 pA4 = Pb[j8], pB4 = Pb[4+j8], qA4 = Qb[j8], qB4 = Qb[4+j8];
        const __half2* phA = reinterpret_cast<const __half2*>(&pA4);
        const __half2* qhA = reinterpret_cast<const __half2*>(&qA4);
        const __half2* phB = reinterpret_cast<const __half2*>(&pB4);
        const __half2* qhB = reinterpret_cast<const __half2*>(&qB4);
        #pragma unroll
        for (int j2 = 0; j2 < 4; j2++) {
            int j = j8*8 + j2*2;
            float2 pfA = __half22float2(phA[j2]);
            float2 qfA = __half22float2(qhA[j2]);
            float2 pfB = __half22float2(phB[j2]);
            float2 qfB = __half22float2(qhB[j2]);
            float c0 = b1s[j];
            c0 = fmaf(a0, wA[j], c0);
            c0 = fmaf(a1, wB[j], c0);
            float c1 = b1s[j+1];
            c1 = fmaf(a0, wA[j+1], c1);
            c1 = fmaf(a1, wB[j+1], c1);
            float hA0 = fsig_fast(fmaf(ewA, w1ds[j],   pfA.x + qfA.x + c0));
            float hA1 = fsig_fast(fmaf(ewA, w1ds[j+1], pfA.y + qfA.y + c1));
            float hB0 = fsig_fast(fmaf(ewB, w1ds[j],   pfB.x + qfB.x + c0));
            float hB1 = fsig_fast(fmaf(ewB, w1ds[j+1], pfB.y + qfB.y + c1));
            ull hdA0 = pack2(hA0, hA0), hdA1 = pack2(hA1, hA1);
            ull hdB0 = pack2(hB0, hB0), hdB1 = pack2(hB1, hB1);
            const ulonglong2* w0 = reinterpret_cast<const ulonglong2*>(&W2s[j*32]);
            const ulonglong2* w1 = reinterpret_cast<const ulonglong2*>(&W2s[(j+1)*32]);
            #pragma unroll
            for (int k4 = 0; k4 < 8; k4++) {
                ulonglong2 wv0 = w0[k4];
                ulonglong2 wv1 = w1[k4];
                FMA_F32X2(accA[k4*2+0], hdA0, wv0.x, accA[k4*2+0]);
                FMA_F32X2(accA[k4*2+1], hdA0, wv0.y, accA[k4*2+1]);
                FMA_F32X2(accB[k4*2+0], hdB0, wv0.x, accB[k4*2+0]);
                FMA_F32X2(accB[k4*2+1], hdB0, wv0.y, accB[k4*2+1]);
                FMA_F32X2(accA[k4*2+0], hdA1, wv1.x, accA[k4*2+0]);
                FMA_F32X2(accA[k4*2+1], hdA1, wv1.y, accA[k4*2+1]);
                FMA_F32X2(accB[k4*2+0], hdB1, wv1.x, accB[k4*2+0]);
                FMA_F32X2(accB[k4*2+1], hdB1, wv1.y, accB[k4*2+1]);
            }
        }
    }
    // sigmoid + fp16 pack
    __align__(16) __half2 oA[16], oB[16];
    #pragma unroll
    for (int k2 = 0; k2 < 16; k2++) {
        float lo, hi;
        unpack2(lo, hi, accA[k2]);
        oA[k2] = __floats2half2_rn(fsig_fast(lo), fsig_fast(hi));
        unpack2(lo, hi, accB[k2]);
        oB[k2] = __floats2half2_rn(fsig_fast(lo), fsig_fast(hi));
    }

    // ---- staged, coalesced output write (reuse PQ buffer) ----
    __syncwarp();                                // all PQ smem reads done
    {
        uint4* os = reinterpret_cast<uint4*>(wb + lane*OUT_STRIDE);
        const uint4* ovA = reinterpret_cast<const uint4*>(oA);
        const uint4* ovB = reinterpret_cast<const uint4*>(oB);
        #pragma unroll
        for (int i = 0; i < 4; i++) { os[i] = ovA[i]; os[4+i] = ovB[i]; }
    }
    __syncwarp();
    {
        // warp's outputs = contiguous 4KB: rows 2p..2p+1 per thread
        size_t gbase = ((size_t)blockIdx.x*128 + (size_t)w*32) * 128;  // bytes
        char* gdst = reinterpret_cast<char*>(g_Eh) + gbase;
        #pragma unroll
        for (int it = 0; it < 8; it++) {
            int u = it*32 + lane;
            uint4 v = *reinterpret_cast<const uint4*>(wb + (u>>3)*OUT_STRIDE + (u&7)*16);
            *reinterpret_cast<uint4*>(gdst + (size_t)u*16) = v;
        }
    }
}

// ---------------- aggregate (gather CSR, fp16, MLP8) + node MLP ----------------
__device__ __forceinline__ float ldE(int entry, int b, int lane) {
    int row = ((entry >> 1) << 3) | b;
    float v = __half2float(__ldg(&g_Eh[(size_t)row*32 + lane]));
    return (entry & 1) ? -v : v;
}

__global__ void __launch_bounds__(256) k_agg_node(const float* __restrict__ Wn,
                                                  const float* __restrict__ bn,
                                                  float* __restrict__ out) {
    __shared__ float Wns[EOUT*NOUT];  // 30x64
    __shared__ float bns[NOUT];
    __shared__ float sA[8][33];
    for (int idx = threadIdx.x; idx < EOUT*NOUT; idx += blockDim.x) Wns[idx] = Wn[idx];
    if (threadIdx.x < NOUT) bns[threadIdx.x] = bn[threadIdx.x];
    __syncthreads();

    int warpId = threadIdx.x >> 5, lane = threadIdx.x & 31;
    int n = blockIdx.x;   // block = node, warp = batch
    int b = warpId;
    int beg = g_off[n], end = g_off[n+1];

    float acc = 0.f;
    int i = beg;
    for (; i + 8 <= end; i += 8) {
        int en[8];
        #pragma unroll
        for (int u = 0; u < 8; u++) en[u] = __ldg(&g_list[i+u]);
        float v[8];
        #pragma unroll
        for (int u = 0; u < 8; u++) v[u] = ldE(en[u], b, lane);
        acc += ((v[0]+v[1]) + (v[2]+v[3])) + ((v[4]+v[5]) + (v[6]+v[7]));
    }
    for (; i < end; i++) acc += ldE(__ldg(&g_list[i]), b, lane);

    sA[warpId][lane] = (lane < EOUT) ? acc : 0.f;
    __syncwarp();

    float o0 = bns[lane], o1 = bns[lane + 32];
    #pragma unroll
    for (int j = 0; j < EOUT; j++) {
        float a = sA[warpId][j];
        o0 += a * Wns[j*NOUT + lane];
        o1 += a * Wns[j*NOUT + lane + 32];
    }
    int ob = ((b*NN + n) << 6) + lane;
    out[ob]      = fsig(o0);
    out[ob + 32] = fsig(o1);
}

// ---------------- launcher ----------------
extern "C" void kernel_launch(void* const* d_in, const int* in_sizes, int n_in,
                              void* d_out, int out_size) {
    const float* x  = (const float*)d_in[0];
    const int*   ei = (const int*)  d_in[1];
    const float* ea = (const float*)d_in[2];
    const float* wm = (const float*)d_in[3];
    const float* ws = (const float*)d_in[4];
    const float* W1 = (const float*)d_in[5];
    const float* b1 = (const float*)d_in[6];
    const float* W2 = (const float*)d_in[7];
    const float* b2 = (const float*)d_in[8];
    const float* Wn = (const float*)d_in[9];
    const float* bn = (const float*)d_in[10];
    float* out = (float*)d_out;

    k_stats_partial<<<256, 256>>>(ea);        // launch 0 (+ zeroes g_cnt)
    k_stats_final<<<1, 256>>>();              // launch 1
    k_node_pre<<<(NB + 255)/256, 256>>>(x, W1, wm, ws);       // launch 2
    k_edge_main<<<(PE/2)/128, 128>>>(ei, ea, W1, b1, W2, b2); // launch 3 (profiled)
    k_hist<<<(EE + 255)/256, 256>>>(ei);      // launch 4
    k_scan<<<1, 1024>>>();                    // launch 5
    k_scatter<<<(EE + 255)/256, 256>>>(ei);   // launch 6
    k_agg_node<<<NN, 256>>>(Wn, bn, out);     // launch 7
}

// round 16
// speedup vs baseline: 1.8608x; 1.1048x over previous
#include <cuda_runtime.h>
#include <cuda_fp16.h>
#include <cuda_bf16.h>
#include <math.h>
#include <cstdint>

#define BB 8
#define NN 10000
#define DD 16
#define EE 320000
#define EH 32
#define EOUT 30
#define NOUT 64
#define NB (NN*BB)            // 80000 (b,n) pairs
#define PE (BB*EE)            // 2,560,000 (b,e) pairs

typedef unsigned long long ull;

// ---------------- device scratch ----------------
__device__ __align__(16) __half g_Ph[NB*32];      // x@W1[0:16] fp16, [n][b][32]
__device__ __align__(16) __half g_Qh[NB*32];      // x@W1[16:32] fp16
__device__ __align__(16) float2 g_SD[NB];         // (speed, direc) per (n,b)
__device__ __align__(16) __half g_Eh[(size_t)PE*32]; // e outputs fp16, [e][b][32]
__device__ double g_part[256*4];
__device__ float g_stats[4];                       // mean0, invstd0, mean1, invstd1
__device__ int g_cnt[NN];
__device__ int g_off[NN+1];
__device__ int g_cursor[NN];
__device__ int g_list[2*EE];                       // signed CSR entries: (e<<1)|is_src

__device__ __forceinline__ float fsig(float x) {
    return __fdividef(1.0f, 1.0f + __expf(-x));
}
__device__ __forceinline__ float fsig_fast(float x) {
    float t;
    asm("tanh.approx.f32 %0, %1;" : "=f"(t) : "f"(x * 0.5f));
    return fmaf(t, 0.5f, 0.5f);
}
__device__ __forceinline__ uint32_t halves2u32(float a, float b) {
    __half2 h = __floats2half2_rn(a, b);
    return *reinterpret_cast<uint32_t*>(&h);
}

// ---------------- stats pass 1 (+ zero g_cnt) ----------------
__global__ void k_stats_partial(const float* __restrict__ ea) {
    __shared__ double sm[256][4];
    int gtid = blockIdx.x*blockDim.x + threadIdx.x;
    if (gtid < NN) g_cnt[gtid] = 0;
    double a0=0, a1=0, a2=0, a3=0;
    for (int i = gtid; i < EE; i += gridDim.x*blockDim.x) {
        float2 v = reinterpret_cast<const float2*>(ea)[i];
        a0 += (double)v.x; a1 += (double)v.x*(double)v.x;
        a2 += (double)v.y; a3 += (double)v.y*(double)v.y;
    }
    int tid = threadIdx.x;
    sm[tid][0]=a0; sm[tid][1]=a1; sm[tid][2]=a2; sm[tid][3]=a3;
    __syncthreads();
    for (int s = 128; s > 0; s >>= 1) {
        if (tid < s) {
            sm[tid][0]+=sm[tid+s][0]; sm[tid][1]+=sm[tid+s][1];
            sm[tid][2]+=sm[tid+s][2]; sm[tid][3]+=sm[tid+s][3];
        }
        __syncthreads();
    }
    if (tid == 0) {
        g_part[blockIdx.x*4+0]=sm[0][0]; g_part[blockIdx.x*4+1]=sm[0][1];
        g_part[blockIdx.x*4+2]=sm[0][2]; g_part[blockIdx.x*4+3]=sm[0][3];
    }
}

// ---------------- stats pass 2 ----------------
__global__ void k_stats_final() {
    __shared__ double sm[256][4];
    int tid = threadIdx.x;
    sm[tid][0]=g_part[tid*4+0]; sm[tid][1]=g_part[tid*4+1];
    sm[tid][2]=g_part[tid*4+2]; sm[tid][3]=g_part[tid*4+3];
    __syncthreads();
    for (int s = 128; s > 0; s >>= 1) {
        if (tid < s) {
            sm[tid][0]+=sm[tid+s][0]; sm[tid][1]+=sm[tid+s][1];
            sm[tid][2]+=sm[tid+s][2]; sm[tid][3]+=sm[tid+s][3];
        }
        __syncthreads();
    }
    if (tid == 0) {
        double s0=sm[0][0], q0=sm[0][1], s1=sm[0][2], q1=sm[0][3];
        double m0 = s0/(double)EE;
        double m1 = s1/(double)EE;
        double v0 = (q0 - s0*s0/(double)EE) / (double)(EE-1);
        double v1 = (q1 - s1*s1/(double)EE) / (double)(EE-1);
        g_stats[0]=(float)m0; g_stats[1]=(float)(1.0/sqrt(v0));
        g_stats[2]=(float)m1; g_stats[3]=(float)(1.0/sqrt(v1));
    }
}

// ---------------- per-(b,n) precompute: P, Q (fp16), speed/direc ----------------
__global__ void k_node_pre(const float* __restrict__ x, const float* __restrict__ W1,
                           const float* __restrict__ wm, const float* __restrict__ ws) {
    __shared__ float W1s[32*32];
    for (int idx = threadIdx.x; idx < 32*32; idx += blockDim.x) W1s[idx] = W1[idx];
    __syncthreads();
    int pair = blockIdx.x*blockDim.x + threadIdx.x;
    if (pair >= NB) return;
    int n = pair >> 3, b = pair & 7;
    const float4* xr = reinterpret_cast<const float4*>(x + ((size_t)b*NN + n)*DD);
    float xv[16];
    #pragma unroll
    for (int d4 = 0; d4 < 4; d4++) {
        float4 v = xr[d4];
        xv[d4*4+0]=v.x; xv[d4*4+1]=v.y; xv[d4*4+2]=v.z; xv[d4*4+3]=v.w;
    }
    __align__(16) __half2 Pt[16], Qt[16];
    #pragma unroll
    for (int j2 = 0; j2 < 16; j2++) {
        float p0=0.f, p1=0.f, q0=0.f, q1=0.f;
        #pragma unroll
        for (int d = 0; d < 16; d++) {
            p0 += xv[d]*W1s[d*32 + j2*2];
            p1 += xv[d]*W1s[d*32 + j2*2 + 1];
            q0 += xv[d]*W1s[(16+d)*32 + j2*2];
            q1 += xv[d]*W1s[(16+d)*32 + j2*2 + 1];
        }
        Pt[j2] = __floats2half2_rn(p0, p1);
        Qt[j2] = __floats2half2_rn(q0, q1);
    }
    uint4* Po = reinterpret_cast<uint4*>(g_Ph + pair*32);
    uint4* Qo = reinterpret_cast<uint4*>(g_Qh + pair*32);
    const uint4* Pv = reinterpret_cast<const uint4*>(Pt);
    const uint4* Qv = reinterpret_cast<const uint4*>(Qt);
    #pragma unroll
    for (int i = 0; i < 4; i++) { Po[i] = Pv[i]; Qo[i] = Qv[i]; }
    g_SD[pair] = make_float2(xv[14]*ws[0] + wm[0], xv[15]*ws[1] + wm[1]);
}

// ---------------- CSR build ----------------
__global__ void k_hist(const int* __restrict__ ei) {
    int e = blockIdx.x*blockDim.x + threadIdx.x;
    if (e >= EE) return;
    atomicAdd(&g_cnt[ei[EE + e]], 1);
    atomicAdd(&g_cnt[ei[e]], 1);
}
__global__ void k_scan() {
    __shared__ int wsum[32];
    __shared__ int sbase_s;
    int tid = threadIdx.x, lane = tid & 31, w = tid >> 5;
    if (tid == 0) sbase_s = 0;
    __syncthreads();
    for (int start = 0; start < NN; start += 1024) {
        int i = start + tid;
        int v = (i < NN) ? g_cnt[i] : 0;
        int s = v;
        #pragma unroll
        for (int d = 1; d < 32; d <<= 1) {
            int t = __shfl_up_sync(0xFFFFFFFFu, s, d);
            if (lane >= d) s += t;
        }
        if (lane == 31) wsum[w] = s;
        __syncthreads();
        if (w == 0) {
            int ws = wsum[lane];
            #pragma unroll
            for (int d = 1; d < 32; d <<= 1) {
                int t = __shfl_up_sync(0xFFFFFFFFu, ws, d);
                if (lane >= d) ws += t;
            }
            wsum[lane] = ws;
        }
        __syncthreads();
        int base = sbase_s;
        int excl = base + s - v + (w > 0 ? wsum[w-1] : 0);
        if (i < NN) { g_off[i] = excl; g_cursor[i] = excl; }
        int total = wsum[31];
        __syncthreads();
        if (tid == 0) sbase_s = base + total;
        __syncthreads();
    }
    if (tid == 0) g_off[NN] = sbase_s;
}
__global__ void k_scatter(const int* __restrict__ ei) {
    int e = blockIdx.x*blockDim.x + threadIdx.x;
    if (e >= EE) return;
    int p1 = atomicAdd(&g_cursor[ei[EE + e]], 1);
    g_list[p1] = (e << 1);           // tgt: +e
    int p2 = atomicAdd(&g_cursor[ei[e]], 1);
    g_list[p2] = (e << 1) | 1;       // src: -e
}

// ================= HMMA edge MLP (mma.sync m16n8k16) =================
// Block = 128 threads (4 warps). Warp owns 64 items (8 edges x 8 batches).
// Per-warp smem buffer (16*528 = 8448B) is used in 3 phases:
//   1) stage 16 P/Q blocks (coalesced LDG)   [8448B]
//   2) A tile 64x32 fp16, 80B row stride     [5120B]  (after h in regs)
//   3) output staging 64 rows x 64B          [5120B]
#define STG_WARP (16*528)
#define A_STRIDE 80

__global__ void __launch_bounds__(128) k_edge_main(const int* __restrict__ ei,
                                                   const float* __restrict__ ea,
                                                   const float* __restrict__ W1,
                                                   const float* __restrict__ b1,
                                                   const float* __restrict__ W2,
                                                   const float* __restrict__ b2) {
    __shared__ __align__(16) float4 W1c[32];       // (wA, wB, w1d, b1) per hidden j
    __shared__ __align__(16) float b2s[32];
    __shared__ float st[4];
    __shared__ __align__(16) __half W2Ts[32*32];   // [n][k] row-major (B col-major)
    __shared__ __align__(16) char stage[4][STG_WARP];

    int tid = threadIdx.x, w = tid >> 5, lane = tid & 31;
    int g = lane >> 2, tig = lane & 3;

    if (tid < 32) {
        W1c[tid] = make_float4(W1[1024+tid], W1[1056+tid], W1[1088+tid], b1[tid]);
        b2s[tid] = (tid < EOUT) ? b2[tid] : 0.f;
    }
    if (tid >= 32 && tid < 36) st[tid-32] = g_stats[tid-32];
    for (int idx = tid; idx < 32*32; idx += 128) {
        int n = idx >> 5, k = idx & 31;
        W2Ts[idx] = __float2half_rn((n < EOUT) ? W2[k*EOUT + n] : 0.f);
    }
    __syncthreads();

    // ---- B fragments (regs for whole kernel): bf[nt][kt][2] ----
    uint32_t bf[4][2][2];
    #pragma unroll
    for (int nt = 0; nt < 4; nt++) {
        #pragma unroll
        for (int kt = 0; kt < 2; kt++) {
            const __half* base = &W2Ts[(nt*8 + g)*32 + kt*16 + 2*tig];
            bf[nt][kt][0] = *reinterpret_cast<const uint32_t*>(base);      // k=2t,2t+1
            bf[nt][kt][1] = *reinterpret_cast<const uint32_t*>(base + 8);  // k+8
        }
    }

    int ebase = blockIdx.x*32 + w*8;
    char* wb = stage[w];

    // ---- phase 1: stage 8 P-blocks + 8 Q-blocks (512B each), coalesced ----
    #pragma unroll
    for (int i = 0; i < 16; i++) {
        int gi = i & 7;
        int nd = (i < 8) ? ei[ebase + gi] : ei[EE + ebase + gi];
        const uint4* src = reinterpret_cast<const uint4*>(
            ((i < 8) ? g_Ph : g_Qh) + (size_t)nd*256);
        *reinterpret_cast<uint4*>(wb + i*528 + lane*16) = src[lane];
    }
    __syncwarp();

    // ---- per-thread h for items (tile rows) 2*lane and 2*lane+1 ----
    int gi = lane >> 2;            // edge within warp's 8
    int b0 = (lane & 3) << 1;      // batch of item A; item B = b0+1
    int eg = ebase + gi;
    int s = ei[eg];
    int sp = (s << 3) | b0;

    float2 eav = reinterpret_cast<const float2*>(ea)[eg];
    float4 sd01 = *reinterpret_cast<const float4*>(&g_SD[sp]);
    float inv_d = __fdividef(3.0f, eav.x);
    float ewA = fmaxf(inv_d * sd01.x * cosf(eav.y - sd01.y), 0.f);
    float ewB = fmaxf(inv_d * sd01.z * cosf(eav.y - sd01.w), 0.f);
    float a0 = (eav.x - st[0]) * st[1];
    float a1 = (eav.y - st[2]) * st[3];

    const uint4* Pb = reinterpret_cast<const uint4*>(wb + gi*528 + b0*64);
    const uint4* Qb = reinterpret_cast<const uint4*>(wb + (8+gi)*528 + b0*64);
    uint32_t h2A[16], h2B[16];
    #pragma unroll
    for (int q = 0; q < 4; q++) {
        uint4 pA4 = Pb[q], pB4 = Pb[4+q], qA4 = Qb[q], qB4 = Qb[4+q];
        const __half2* phA = reinterpret_cast<const __half2*>(&pA4);
        const __half2* qhA = reinterpret_cast<const __half2*>(&qA4);
        const __half2* phB = reinterpret_cast<const __half2*>(&pB4);
        const __half2* qhB = reinterpret_cast<const __half2*>(&qB4);
        #pragma unroll
        for (int r = 0; r < 4; r++) {
            int j = q*8 + r*2;
            float2 pfA = __half22float2(phA[r]);
            float2 qfA = __half22float2(qhA[r]);
            float2 pfB = __half22float2(phB[r]);
            float2 qfB = __half22float2(qhB[r]);
            float4 w0 = W1c[j], w1 = W1c[j+1];
            float c0 = fmaf(a0, w0.x, fmaf(a1, w0.y, w0.w));
            float c1 = fmaf(a0, w1.x, fmaf(a1, w1.y, w1.w));
            float zA0 = fmaf(ewA, w0.z, pfA.x + qfA.x + c0);
            float zA1 = fmaf(ewA, w1.z, pfA.y + qfA.y + c1);
            float zB0 = fmaf(ewB, w0.z, pfB.x + qfB.x + c0);
            float zB1 = fmaf(ewB, w1.z, pfB.y + qfB.y + c1);
            h2A[j >> 1] = halves2u32(fsig_fast(zA0), fsig_fast(zA1));
            h2B[j >> 1] = halves2u32(fsig_fast(zB0), fsig_fast(zB1));
        }
    }
    __syncwarp();   // all staged P/Q reads complete before buffer reuse

    // ---- phase 2: write A tile rows 2*lane, 2*lane+1 (80B stride) ----
    {
        char* rA = wb + (2*lane)*A_STRIDE;
        char* rB = rA + A_STRIDE;
        const uint4* vA = reinterpret_cast<const uint4*>(h2A);
        const uint4* vB = reinterpret_cast<const uint4*>(h2B);
        #pragma unroll
        for (int c = 0; c < 4; c++) {
            *reinterpret_cast<uint4*>(rA + c*16) = vA[c];
            *reinterpret_cast<uint4*>(rB + c*16) = vB[c];
        }
    }
    __syncwarp();

    // ---- MMA: 4 m-tiles x 4 n-tiles x 2 k-tiles ----
    float acc[4][4][4];
    #pragma unroll
    for (int mt = 0; mt < 4; mt++)
        #pragma unroll
        for (int nt = 0; nt < 4; nt++)
            #pragma unroll
            for (int c = 0; c < 4; c++) acc[mt][nt][c] = 0.f;

    #pragma unroll
    for (int mt = 0; mt < 4; mt++) {
        uint32_t af[2][4];
        #pragma unroll
        for (int kt = 0; kt < 2; kt++) {
            const char* base = wb + (mt*16 + g)*A_STRIDE + (kt*16 + 2*tig)*2;
            af[kt][0] = *reinterpret_cast<const uint32_t*>(base);                 // (g,   2t)
            af[kt][1] = *reinterpret_cast<const uint32_t*>(base + 8*A_STRIDE);    // (g+8, 2t)
            af[kt][2] = *reinterpret_cast<const uint32_t*>(base + 16);            // (g,   2t+8)
            af[kt][3] = *reinterpret_cast<const uint32_t*>(base + 8*A_STRIDE + 16);
        }
        #pragma unroll
        for (int nt = 0; nt < 4; nt++) {
            #pragma unroll
            for (int kt = 0; kt < 2; kt++) {
                asm volatile(
                    "mma.sync.aligned.m16n8k16.row.col.f32.f16.f16.f32 "
                    "{%0,%1,%2,%3}, {%4,%5,%6,%7}, {%8,%9}, {%0,%1,%2,%3};"
                    : "+f"(acc[mt][nt][0]), "+f"(acc[mt][nt][1]),
                      "+f"(acc[mt][nt][2]), "+f"(acc[mt][nt][3])
                    : "r"(af[kt][0]), "r"(af[kt][1]), "r"(af[kt][2]), "r"(af[kt][3]),
                      "r"(bf[nt][kt][0]), "r"(bf[nt][kt][1]));
            }
        }
    }
    __syncwarp();   // all A-frag reads done before overwriting tile

    // ---- phase 3: epilogue bias + sigmoid -> fp16 pairs into tile ----
    #pragma unroll
    for (int mt = 0; mt < 4; mt++) {
        #pragma unroll
        for (int nt = 0; nt < 4; nt++) {
            int col = nt*8 + 2*tig;
            float bb0 = b2s[col], bb1 = b2s[col+1];
            int r0 = mt*16 + g;
            uint32_t p0 = halves2u32(fsig_fast(acc[mt][nt][0] + bb0),
                                     fsig_fast(acc[mt][nt][1] + bb1));
            uint32_t p1 = halves2u32(fsig_fast(acc[mt][nt][2] + bb0),
                                     fsig_fast(acc[mt][nt][3] + bb1));
            *reinterpret_cast<uint32_t*>(wb + r0*A_STRIDE + col*2) = p0;
            *reinterpret_cast<uint32_t*>(wb + (r0+8)*A_STRIDE + col*2) = p1;
        }
    }
    __syncwarp();

    // ---- coalesced copy: 64 rows x 64B -> contiguous 4KB in g_Eh ----
    {
        char* gdst = reinterpret_cast<char*>(g_Eh)
                   + ((size_t)blockIdx.x*256 + (size_t)w*64) * 64;
        #pragma unroll
        for (int it = 0; it < 8; it++) {
            int u = it*32 + lane;           // 16B unit: row = u/4, chunk = u%4
            uint4 v = *reinterpret_cast<const uint4*>(wb + (u>>2)*A_STRIDE + (u&3)*16);
            *reinterpret_cast<uint4*>(gdst + (size_t)u*16) = v;
        }
    }
}

// ---------------- aggregate (gather CSR, fp16, MLP8) + node MLP ----------------
__device__ __forceinline__ float ldE(int entry, int b, int lane) {
    int row = ((entry >> 1) << 3) | b;
    float v = __half2float(__ldg(&g_Eh[(size_t)row*32 + lane]));
    return (entry & 1) ? -v : v;
}

__global__ void __launch_bounds__(256) k_agg_node(const float* __restrict__ Wn,
                                                  const float* __restrict__ bn,
                                                  float* __restrict__ out) {
    __shared__ float Wns[EOUT*NOUT];  // 30x64
    __shared__ float bns[NOUT];
    __shared__ float sA[8][33];
    for (int idx = threadIdx.x; idx < EOUT*NOUT; idx += blockDim.x) Wns[idx] = Wn[idx];
    if (threadIdx.x < NOUT) bns[threadIdx.x] = bn[threadIdx.x];
    __syncthreads();

    int warpId = threadIdx.x >> 5, lane = threadIdx.x & 31;
    int n = blockIdx.x;   // block = node, warp = batch
    int b = warpId;
    int beg = g_off[n], end = g_off[n+1];

    float acc = 0.f;
    int i = beg;
    for (; i + 8 <= end; i += 8) {
        int en[8];
        #pragma unroll
        for (int u = 0; u < 8; u++) en[u] = __ldg(&g_list[i+u]);
        float v[8];
        #pragma unroll
        for (int u = 0; u < 8; u++) v[u] = ldE(en[u], b, lane);
        acc += ((v[0]+v[1]) + (v[2]+v[3])) + ((v[4]+v[5]) + (v[6]+v[7]));
    }
    for (; i < end; i++) acc += ldE(__ldg(&g_list[i]), b, lane);

    sA[warpId][lane] = (lane < EOUT) ? acc : 0.f;
    __syncwarp();

    float o0 = bns[lane], o1 = bns[lane + 32];
    #pragma unroll
    for (int j = 0; j < EOUT; j++) {
        float a = sA[warpId][j];
        o0 += a * Wns[j*NOUT + lane];
        o1 += a * Wns[j*NOUT + lane + 32];
    }
    int ob = ((b*NN + n) << 6) + lane;
    out[ob]      = fsig(o0);
    out[ob + 32] = fsig(o1);
}

// ---------------- launcher ----------------
extern "C" void kernel_launch(void* const* d_in, const int* in_sizes, int n_in,
                              void* d_out, int out_size) {
    const float* x  = (const float*)d_in[0];
    const int*   ei = (const int*)  d_in[1];
    const float* ea = (const float*)d_in[2];
    const float* wm = (const float*)d_in[3];
    const float* ws = (const float*)d_in[4];
    const float* W1 = (const float*)d_in[5];
    const float* b1 = (const float*)d_in[6];
    const float* W2 = (const float*)d_in[7];
    const float* b2 = (const float*)d_in[8];
    const float* Wn = (const float*)d_in[9];
    const float* bn = (const float*)d_in[10];
    float* out = (float*)d_out;

    k_stats_partial<<<256, 256>>>(ea);        // launch 0 (+ zeroes g_cnt)
    k_stats_final<<<1, 256>>>();              // launch 1
    k_node_pre<<<(NB + 255)/256, 256>>>(x, W1, wm, ws);       // launch 2
    k_edge_main<<<PE/256, 128>>>(ei, ea, W1, b1, W2, b2);     // launch 3 (profiled)
    k_hist<<<(EE + 255)/256, 256>>>(ei);      // launch 4
    k_scan<<<1, 1024>>>();                    // launch 5
    k_scatter<<<(EE + 255)/256, 256>>>(ei);   // launch 6
    k_agg_node<<<NN, 256>>>(Wn, bn, out);     // launch 7
}